// round 2
// baseline (speedup 1.0000x reference)
#include <cuda_runtime.h>
#include <math.h>

#define NE 50000
#define NR 64
#define NT 400000

// Scratch (static __device__ — no runtime allocation)
__device__ float    g_T[NE * 256];    // [ent][0:128]=emb@Wa2 (head/att), [128:256]=emb@Wg1+bg (head/msg)
__device__ float    g_P1[NE * 128];   // emb@Wa1 + ba (tail/att)
__device__ float    g_RG[NR * 256];   // [rel][0:128]=emb_rel@Wa3, [128:256]=emb_rel@Wg2
__device__ int      g_rowptr[NE + 1];
__device__ int      g_cursor[NE];
__device__ unsigned g_elist[NT];      // head | (rel<<16)

// ---------------- CSR build ----------------
__global__ void k_zero() {
    int i = blockIdx.x * blockDim.x + threadIdx.x;
    if (i <= NE) g_rowptr[i] = 0;
}

__global__ void k_count(const int* __restrict__ trip) {
    int e = blockIdx.x * blockDim.x + threadIdx.x;
    if (e < NT) atomicAdd(&g_rowptr[trip[3 * e + 2]], 1);
}

__global__ void k_scan() {  // single block, 1024 threads: exclusive scan of counts -> rowptr
    __shared__ int warp_off[32];
    __shared__ int s_carry;
    int tid = threadIdx.x, lane = tid & 31, wid = tid >> 5;
    if (tid == 0) s_carry = 0;
    __syncthreads();
    for (int base = 0; base < NE; base += 1024) {
        int idx = base + tid;
        int v = (idx < NE) ? g_rowptr[idx] : 0;
        int incl = v;
        #pragma unroll
        for (int o = 1; o < 32; o <<= 1) {
            int u = __shfl_up_sync(0xffffffffu, incl, o);
            if (lane >= o) incl += u;
        }
        if (lane == 31) warp_off[wid] = incl;
        __syncthreads();
        if (wid == 0) {
            int w = warp_off[lane];
            int wi = w;
            #pragma unroll
            for (int o = 1; o < 32; o <<= 1) {
                int u = __shfl_up_sync(0xffffffffu, wi, o);
                if (lane >= o) wi += u;
            }
            warp_off[lane] = wi - w;  // exclusive warp offsets
        }
        __syncthreads();
        int excl = s_carry + warp_off[wid] + (incl - v);
        if (idx < NE) { g_rowptr[idx] = excl; g_cursor[idx] = excl; }
        __syncthreads();
        if (tid == 1023) s_carry = excl + v;
        __syncthreads();
    }
    if (tid == 0) g_rowptr[NE] = s_carry;
}

__global__ void k_scatter(const int* __restrict__ trip) {
    int e = blockIdx.x * blockDim.x + threadIdx.x;
    if (e < NT) {
        int h = trip[3 * e], r = trip[3 * e + 1], t = trip[3 * e + 2];
        int pos = atomicAdd(&g_cursor[t], 1);
        g_elist[pos] = (unsigned)h | ((unsigned)r << 16);
    }
}

// ---------------- tiny relation GEMM: Ra = emb_rel@Wa[256:384], Gr = emb_rel@Wg[128:256] ----------------
__global__ void k_relgemm(const float* __restrict__ emb_rel,
                          const float* __restrict__ Wa,
                          const float* __restrict__ Wg) {
    __shared__ float er[128];
    int r = blockIdx.x;
    int tid = threadIdx.x;  // 256
    if (tid < 128) er[tid] = emb_rel[r * 128 + tid];
    __syncthreads();
    int j = tid & 127;
    const float* W = (tid < 128) ? (Wa + 256 * 128) : (Wg + 128 * 128);
    float acc = 0.f;
    #pragma unroll 8
    for (int k = 0; k < 128; k++) acc += er[k] * W[k * 128 + j];
    g_RG[r * 256 + tid] = acc;
}

// ---------------- entity GEMM: [50000x128] @ [128x128] x3 column-groups ----------------
// y=0: Wa[0:128]   -> g_P1 (+ba)       (tail attention term)
// y=1: Wa[128:256] -> g_T[:, 0:128]    (head attention term)
// y=2: Wg[0:128]   -> g_T[:,128:256] (+bg)  (head message term)
__global__ __launch_bounds__(256) void k_entgemm(
    const float* __restrict__ A,
    const float* __restrict__ Wa, const float* __restrict__ ba,
    const float* __restrict__ Wg, const float* __restrict__ bg) {
    const int M = NE;
    __shared__ float As[16 * 132];  // [k][m], padded
    __shared__ float Bs[16 * 128];  // [k][n]

    int y = blockIdx.y;
    const float* B = (y == 0) ? Wa : (y == 1 ? (Wa + 128 * 128) : Wg);
    const float* bias = (y == 0) ? ba : (y == 2 ? bg : nullptr);

    int tid = threadIdx.x;
    int tCol = tid & 15, tRow = tid >> 4;
    int rowBase = blockIdx.x * 128;

    int aRow = tid >> 2;          // 0..63
    int aCol = (tid & 3) * 4;     // k offset within 16
    int bRow = tid >> 5;          // 0..7
    int bCol = (tid & 31) * 4;

    float acc[8][8];
    #pragma unroll
    for (int i = 0; i < 8; i++)
        #pragma unroll
        for (int j = 0; j < 8; j++) acc[i][j] = 0.f;

    for (int k0 = 0; k0 < 128; k0 += 16) {
        #pragma unroll
        for (int p = 0; p < 2; p++) {
            int m = aRow + p * 64;
            int gr = rowBase + m;
            float4 v = make_float4(0.f, 0.f, 0.f, 0.f);
            if (gr < M) v = *(const float4*)(A + (long)gr * 128 + k0 + aCol);
            As[(aCol + 0) * 132 + m] = v.x;
            As[(aCol + 1) * 132 + m] = v.y;
            As[(aCol + 2) * 132 + m] = v.z;
            As[(aCol + 3) * 132 + m] = v.w;
        }
        #pragma unroll
        for (int p = 0; p < 2; p++) {
            int kk = bRow + p * 8;
            *(float4*)(Bs + kk * 128 + bCol) = *(const float4*)(B + (k0 + kk) * 128 + bCol);
        }
        __syncthreads();
        #pragma unroll
        for (int k = 0; k < 16; k++) {
            float rM[8], rN[8];
            #pragma unroll
            for (int i = 0; i < 8; i++) rM[i] = As[k * 132 + tRow * 8 + i];
            #pragma unroll
            for (int j = 0; j < 8; j++) rN[j] = Bs[k * 128 + tCol * 8 + j];
            #pragma unroll
            for (int i = 0; i < 8; i++)
                #pragma unroll
                for (int j = 0; j < 8; j++) acc[i][j] += rM[i] * rN[j];
        }
        __syncthreads();
    }

    float bb[8];
    #pragma unroll
    for (int j = 0; j < 8; j++) bb[j] = bias ? bias[tCol * 8 + j] : 0.f;

    float* dstBase = (y == 0) ? g_P1 : g_T;
    int stride = (y == 0) ? 128 : 256;
    int coff = (y == 2) ? 128 : 0;

    #pragma unroll
    for (int i = 0; i < 8; i++) {
        int gr = rowBase + tRow * 8 + i;
        if (gr < M) {
            float* p = dstBase + (long)gr * stride + coff + tCol * 8;
            float4 v0 = make_float4(acc[i][0] + bb[0], acc[i][1] + bb[1],
                                    acc[i][2] + bb[2], acc[i][3] + bb[3]);
            float4 v1 = make_float4(acc[i][4] + bb[4], acc[i][5] + bb[5],
                                    acc[i][6] + bb[6], acc[i][7] + bb[7]);
            *(float4*)p = v0;
            *(float4*)(p + 4) = v1;
        }
    }
}

// ---------------- fused edge kernel: one warp per entity, online softmax ----------------
__global__ __launch_bounds__(256) void k_main(const float* __restrict__ av_g,
                                              float* __restrict__ out) {
    int tid = threadIdx.x, lane = tid & 31, warp = tid >> 5;
    float4 av = ((const float4*)av_g)[lane];  // attn_vec channels [4*lane, 4*lane+4)
    const float4* RG = (const float4*)g_RG;

    int gw = blockIdx.x * 8 + warp;
    int nw = gridDim.x * 8;
    for (int ent = gw; ent < NE; ent += nw) {
        int beg = g_rowptr[ent], end = g_rowptr[ent + 1];
        float4 p1 = *(const float4*)(g_P1 + (long)ent * 128 + lane * 4);
        float4 sA = make_float4(0.f, 0.f, 0.f, 0.f);
        float4 sG = sA, acc = sA;
        float m = -1e30f, s = 0.f;

        for (int i = beg; i < end; i++) {
            unsigned pk = __ldg(&g_elist[i]);
            int h = pk & 0xFFFFu;
            int r = pk >> 16;
            const float4* T4 = (const float4*)(g_T + (long)h * 256);
            float4 tlo = __ldg(&T4[lane]);
            float4 thi = __ldg(&T4[32 + lane]);
            float4 ra = __ldg(&RG[r * 64 + lane]);
            float4 gr = __ldg(&RG[r * 64 + 32 + lane]);
            sA.x += ra.x; sA.y += ra.y; sA.z += ra.z; sA.w += ra.w;
            sG.x += gr.x; sG.y += gr.y; sG.z += gr.z; sG.w += gr.w;

            float hx = tanhf(p1.x + tlo.x + ra.x);
            float hy = tanhf(p1.y + tlo.y + ra.y);
            float hz = tanhf(p1.z + tlo.z + ra.z);
            float hw = tanhf(p1.w + tlo.w + ra.w);
            float part = hx * av.x + hy * av.y + hz * av.z + hw * av.w;
            part += __shfl_xor_sync(0xffffffffu, part, 1);
            part += __shfl_xor_sync(0xffffffffu, part, 2);

            float nm = fmaxf(m, part);
            float f = __expf(m - nm);
            float w = __expf(part - nm);
            s = s * f + w;
            acc.x = acc.x * f + w * (thi.x + gr.x);
            acc.y = acc.y * f + w * (thi.y + gr.y);
            acc.z = acc.z * f + w * (thi.z + gr.z);
            acc.w = acc.w * f + w * (thi.w + gr.w);
            m = nm;
        }
        // self-loop edge: rel term = (sum Ra[rel]) / freq  (freq==0 -> 0, matches ref)
        {
            float inv = (end > beg) ? 1.f / (float)(end - beg) : 1.f;
            const float4* T4 = (const float4*)(g_T + (long)ent * 256);
            float4 tlo = __ldg(&T4[lane]);
            float4 thi = __ldg(&T4[32 + lane]);
            float rax = sA.x * inv, ray = sA.y * inv, raz = sA.z * inv, raw = sA.w * inv;
            float grx = sG.x * inv, gry = sG.y * inv, grz = sG.z * inv, grw = sG.w * inv;

            float hx = tanhf(p1.x + tlo.x + rax);
            float hy = tanhf(p1.y + tlo.y + ray);
            float hz = tanhf(p1.z + tlo.z + raz);
            float hw = tanhf(p1.w + tlo.w + raw);
            float part = hx * av.x + hy * av.y + hz * av.z + hw * av.w;
            part += __shfl_xor_sync(0xffffffffu, part, 1);
            part += __shfl_xor_sync(0xffffffffu, part, 2);

            float nm = fmaxf(m, part);
            float f = __expf(m - nm);
            float w = __expf(part - nm);
            s = s * f + w;
            acc.x = acc.x * f + w * (thi.x + grx);
            acc.y = acc.y * f + w * (thi.y + gry);
            acc.z = acc.z * f + w * (thi.z + grz);
            acc.w = acc.w * f + w * (thi.w + grw);
        }
        float invs = 1.f / (s + 1e-16f);
        float4 o = make_float4(acc.x * invs, acc.y * invs, acc.z * invs, acc.w * invs);
        *(float4*)(out + (long)ent * 128 + lane * 4) = o;
    }
}

extern "C" void kernel_launch(void* const* d_in, const int* in_sizes, int n_in,
                              void* d_out, int out_size) {
    const float* emb_ent = (const float*)d_in[0];
    const float* emb_rel = (const float*)d_in[1];
    const int*   trip    = (const int*)d_in[2];
    const float* Wa      = (const float*)d_in[3];
    const float* ba      = (const float*)d_in[4];
    const float* av      = (const float*)d_in[5];
    const float* Wg      = (const float*)d_in[6];
    const float* bg      = (const float*)d_in[7];
    float* out = (float*)d_out;

    k_zero<<<(NE + 1 + 255) / 256, 256>>>();
    k_count<<<(NT + 255) / 256, 256>>>(trip);
    k_scan<<<1, 1024>>>();
    k_scatter<<<(NT + 255) / 256, 256>>>(trip);
    k_relgemm<<<NR, 256>>>(emb_rel, Wa, Wg);
    dim3 g((NE + 127) / 128, 3);
    k_entgemm<<<g, 256>>>(emb_ent, Wa, ba, Wg, bg);
    k_main<<<592, 256>>>(av, out);
}

// round 4
// speedup vs baseline: 1.0034x; 1.0034x over previous
#include <cuda_runtime.h>
#include <math.h>

#define NE 50000
#define NR 64
#define NT 400000

typedef unsigned long long u64;

// Scratch (static __device__ — no runtime allocation)
__device__ float    g_T[NE * 256];    // [ent][0:128]=emb@Wa2 (head/att), [128:256]=emb@Wg1+bg (head/msg)
__device__ float    g_P1[NE * 128];   // emb@Wa1 + ba (tail/att)
__device__ float    g_RG[NR * 256];   // [rel][0:128]=emb_rel@Wa3, [128:256]=emb_rel@Wg2
__device__ int      g_rowptr[NE + 1];
__device__ int      g_cursor[NE];
__device__ unsigned g_elist[NT];      // head | (rel<<16)

// ---------------- packed f32x2 helpers ----------------
__device__ __forceinline__ u64 pack2(float lo, float hi) {
    u64 r; asm("mov.b64 %0, {%1,%2};" : "=l"(r) : "f"(lo), "f"(hi)); return r;
}
__device__ __forceinline__ void fma2(u64& d, u64 a, u64 b) {
    asm("fma.rn.f32x2 %0, %1, %2, %0;" : "+l"(d) : "l"(a), "l"(b));
}
__device__ __forceinline__ float2 unpack2(u64 v) {
    float2 f; asm("mov.b64 {%0,%1}, %2;" : "=f"(f.x), "=f"(f.y) : "l"(v)); return f;
}

// ---------------- CSR build ----------------
__global__ void k_zero() {
    int i = blockIdx.x * blockDim.x + threadIdx.x;
    if (i <= NE) g_rowptr[i] = 0;
}

__global__ void k_count(const int* __restrict__ trip) {
    int e = blockIdx.x * blockDim.x + threadIdx.x;
    if (e < NT) atomicAdd(&g_rowptr[trip[3 * e + 2]], 1);
}

__global__ void k_scan() {  // single block, 1024 threads: exclusive scan of counts -> rowptr
    __shared__ int warp_off[32];
    __shared__ int s_carry;
    int tid = threadIdx.x, lane = tid & 31, wid = tid >> 5;
    if (tid == 0) s_carry = 0;
    __syncthreads();
    for (int base = 0; base < NE; base += 1024) {
        int idx = base + tid;
        int v = (idx < NE) ? g_rowptr[idx] : 0;
        int incl = v;
        #pragma unroll
        for (int o = 1; o < 32; o <<= 1) {
            int u = __shfl_up_sync(0xffffffffu, incl, o);
            if (lane >= o) incl += u;
        }
        if (lane == 31) warp_off[wid] = incl;
        __syncthreads();
        if (wid == 0) {
            int w = warp_off[lane];
            int wi = w;
            #pragma unroll
            for (int o = 1; o < 32; o <<= 1) {
                int u = __shfl_up_sync(0xffffffffu, wi, o);
                if (lane >= o) wi += u;
            }
            warp_off[lane] = wi - w;  // exclusive warp offsets
        }
        __syncthreads();
        int excl = s_carry + warp_off[wid] + (incl - v);
        if (idx < NE) { g_rowptr[idx] = excl; g_cursor[idx] = excl; }
        __syncthreads();
        if (tid == 1023) s_carry = excl + v;
        __syncthreads();
    }
    if (tid == 0) g_rowptr[NE] = s_carry;
}

__global__ void k_scatter(const int* __restrict__ trip) {
    int e = blockIdx.x * blockDim.x + threadIdx.x;
    if (e < NT) {
        int h = trip[3 * e], r = trip[3 * e + 1], t = trip[3 * e + 2];
        int pos = atomicAdd(&g_cursor[t], 1);
        g_elist[pos] = (unsigned)h | ((unsigned)r << 16);
    }
}

// ---------------- tiny relation GEMM: Ra = emb_rel@Wa[256:384], Gr = emb_rel@Wg[128:256] ----------------
__global__ void k_relgemm(const float* __restrict__ emb_rel,
                          const float* __restrict__ Wa,
                          const float* __restrict__ Wg) {
    __shared__ float er[128];
    int r = blockIdx.x;
    int tid = threadIdx.x;  // 256
    if (tid < 128) er[tid] = emb_rel[r * 128 + tid];
    __syncthreads();
    int j = tid & 127;
    const float* W = (tid < 128) ? (Wa + 256 * 128) : (Wg + 128 * 128);
    float acc = 0.f;
    #pragma unroll 8
    for (int k = 0; k < 128; k++) acc += er[k] * W[k * 128 + j];
    g_RG[r * 256 + tid] = acc;
}

// ---------------- entity GEMM: [50000x128] @ [128x128] x3 column-groups ----------------
// y=0: Wa[0:128]   -> g_P1 (+ba)       (tail attention term)
// y=1: Wa[128:256] -> g_T[:, 0:128]    (head attention term)
// y=2: Wg[0:128]   -> g_T[:,128:256] (+bg)  (head message term)
// Inner product uses packed fma.rn.f32x2: M-dim pairs packed (A operand is a
// 64-bit aligned shared load), B operand broadcast-packed once per k-step.
__global__ __launch_bounds__(256) void k_entgemm(
    const float* __restrict__ A,
    const float* __restrict__ Wa, const float* __restrict__ ba,
    const float* __restrict__ Wg, const float* __restrict__ bg) {
    const int M = NE;
    __shared__ float As[16 * 132];  // [k][m], padded (132 keeps 8B alignment for pair loads)
    __shared__ float Bs[16 * 128];  // [k][n]

    int y = blockIdx.y;
    const float* B = (y == 0) ? Wa : (y == 1 ? (Wa + 128 * 128) : Wg);
    const float* bias = (y == 0) ? ba : (y == 2 ? bg : nullptr);

    int tid = threadIdx.x;
    int tCol = tid & 15, tRow = tid >> 4;
    int rowBase = blockIdx.x * 128;

    int aRow = tid >> 2;          // 0..63
    int aCol = (tid & 3) * 4;     // k offset within 16
    int bRow = tid >> 5;          // 0..7
    int bCol = (tid & 31) * 4;

    u64 acc[4][8];                // [m-pair][n]
    const u64 z2 = pack2(0.f, 0.f);
    #pragma unroll
    for (int i = 0; i < 4; i++)
        #pragma unroll
        for (int j = 0; j < 8; j++) acc[i][j] = z2;

    for (int k0 = 0; k0 < 128; k0 += 16) {
        #pragma unroll
        for (int p = 0; p < 2; p++) {
            int m = aRow + p * 64;
            int gr = rowBase + m;
            float4 v = make_float4(0.f, 0.f, 0.f, 0.f);
            if (gr < M) v = *(const float4*)(A + (long)gr * 128 + k0 + aCol);
            As[(aCol + 0) * 132 + m] = v.x;
            As[(aCol + 1) * 132 + m] = v.y;
            As[(aCol + 2) * 132 + m] = v.z;
            As[(aCol + 3) * 132 + m] = v.w;
        }
        #pragma unroll
        for (int p = 0; p < 2; p++) {
            int kk = bRow + p * 8;
            *(float4*)(Bs + kk * 128 + bCol) = *(const float4*)(B + (k0 + kk) * 128 + bCol);
        }
        __syncthreads();
        #pragma unroll
        for (int k = 0; k < 16; k++) {
            // A: 4 packed m-pairs, straight 64-bit loads from shared
            u64 a2[4];
            const u64* ap = (const u64*)(As + k * 132 + tRow * 8);
            #pragma unroll
            for (int i = 0; i < 4; i++) a2[i] = ap[i];
            // B: 8 n-values, broadcast-packed (ALU pipe, overlaps FMA pipe)
            float4 n0 = *(const float4*)(Bs + k * 128 + tCol * 8);
            float4 n1 = *(const float4*)(Bs + k * 128 + tCol * 8 + 4);
            u64 b2[8];
            b2[0] = pack2(n0.x, n0.x); b2[1] = pack2(n0.y, n0.y);
            b2[2] = pack2(n0.z, n0.z); b2[3] = pack2(n0.w, n0.w);
            b2[4] = pack2(n1.x, n1.x); b2[5] = pack2(n1.y, n1.y);
            b2[6] = pack2(n1.z, n1.z); b2[7] = pack2(n1.w, n1.w);
            #pragma unroll
            for (int i = 0; i < 4; i++)
                #pragma unroll
                for (int j = 0; j < 8; j++) fma2(acc[i][j], a2[i], b2[j]);
        }
        __syncthreads();
    }

    float bb[8];
    #pragma unroll
    for (int j = 0; j < 8; j++) bb[j] = bias ? bias[tCol * 8 + j] : 0.f;

    float* dstBase = (y == 0) ? g_P1 : g_T;
    int stride = (y == 0) ? 128 : 256;
    int coff = (y == 2) ? 128 : 0;

    #pragma unroll
    for (int i = 0; i < 4; i++) {
        float2 u[8];
        #pragma unroll
        for (int j = 0; j < 8; j++) u[j] = unpack2(acc[i][j]);
        #pragma unroll
        for (int p = 0; p < 2; p++) {
            int gr = rowBase + tRow * 8 + 2 * i + p;
            if (gr < M) {
                float* dp = dstBase + (long)gr * stride + coff + tCol * 8;
                float r0 = p ? u[0].y : u[0].x, r1 = p ? u[1].y : u[1].x;
                float r2 = p ? u[2].y : u[2].x, r3 = p ? u[3].y : u[3].x;
                float r4 = p ? u[4].y : u[4].x, r5 = p ? u[5].y : u[5].x;
                float r6 = p ? u[6].y : u[6].x, r7 = p ? u[7].y : u[7].x;
                float4 v0 = make_float4(r0 + bb[0], r1 + bb[1], r2 + bb[2], r3 + bb[3]);
                float4 v1 = make_float4(r4 + bb[4], r5 + bb[5], r6 + bb[6], r7 + bb[7]);
                *(float4*)dp = v0;
                *(float4*)(dp + 4) = v1;
            }
        }
    }
}

// ---------------- fused edge kernel: one warp per entity, online softmax ----------------
__global__ __launch_bounds__(256) void k_main(const float* __restrict__ av_g,
                                              float* __restrict__ out) {
    int tid = threadIdx.x, lane = tid & 31, warp = tid >> 5;
    float4 av = ((const float4*)av_g)[lane];  // attn_vec channels [4*lane, 4*lane+4)
    const float4* RG = (const float4*)g_RG;

    int gw = blockIdx.x * 8 + warp;
    int nw = gridDim.x * 8;
    for (int ent = gw; ent < NE; ent += nw) {
        int beg = g_rowptr[ent], end = g_rowptr[ent + 1];
        float4 p1 = *(const float4*)(g_P1 + (long)ent * 128 + lane * 4);
        float4 sA = make_float4(0.f, 0.f, 0.f, 0.f);
        float4 sG = sA, acc = sA;
        float m = -1e30f, s = 0.f;

        for (int i = beg; i < end; i++) {
            unsigned pk = __ldg(&g_elist[i]);
            int h = pk & 0xFFFFu;
            int r = pk >> 16;
            const float4* T4 = (const float4*)(g_T + (long)h * 256);
            float4 tlo = __ldg(&T4[lane]);
            float4 thi = __ldg(&T4[32 + lane]);
            float4 ra = __ldg(&RG[r * 64 + lane]);
            float4 gr = __ldg(&RG[r * 64 + 32 + lane]);
            sA.x += ra.x; sA.y += ra.y; sA.z += ra.z; sA.w += ra.w;
            sG.x += gr.x; sG.y += gr.y; sG.z += gr.z; sG.w += gr.w;

            float hx = tanhf(p1.x + tlo.x + ra.x);
            float hy = tanhf(p1.y + tlo.y + ra.y);
            float hz = tanhf(p1.z + tlo.z + ra.z);
            float hw = tanhf(p1.w + tlo.w + ra.w);
            float part = hx * av.x + hy * av.y + hz * av.z + hw * av.w;
            part += __shfl_xor_sync(0xffffffffu, part, 1);
            part += __shfl_xor_sync(0xffffffffu, part, 2);

            float nm = fmaxf(m, part);
            float f = __expf(m - nm);
            float w = __expf(part - nm);
            s = s * f + w;
            acc.x = acc.x * f + w * (thi.x + gr.x);
            acc.y = acc.y * f + w * (thi.y + gr.y);
            acc.z = acc.z * f + w * (thi.z + gr.z);
            acc.w = acc.w * f + w * (thi.w + gr.w);
            m = nm;
        }
        // self-loop edge: rel term = (sum Ra[rel]) / freq  (freq==0 -> 0, matches ref)
        {
            float inv = (end > beg) ? 1.f / (float)(end - beg) : 1.f;
            const float4* T4 = (const float4*)(g_T + (long)ent * 256);
            float4 tlo = __ldg(&T4[lane]);
            float4 thi = __ldg(&T4[32 + lane]);
            float rax = sA.x * inv, ray = sA.y * inv, raz = sA.z * inv, raw = sA.w * inv;
            float grx = sG.x * inv, gry = sG.y * inv, grz = sG.z * inv, grw = sG.w * inv;

            float hx = tanhf(p1.x + tlo.x + rax);
            float hy = tanhf(p1.y + tlo.y + ray);
            float hz = tanhf(p1.z + tlo.z + raz);
            float hw = tanhf(p1.w + tlo.w + raw);
            float part = hx * av.x + hy * av.y + hz * av.z + hw * av.w;
            part += __shfl_xor_sync(0xffffffffu, part, 1);
            part += __shfl_xor_sync(0xffffffffu, part, 2);

            float nm = fmaxf(m, part);
            float f = __expf(m - nm);
            float w = __expf(part - nm);
            s = s * f + w;
            acc.x = acc.x * f + w * (thi.x + grx);
            acc.y = acc.y * f + w * (thi.y + gry);
            acc.z = acc.z * f + w * (thi.z + grz);
            acc.w = acc.w * f + w * (thi.w + grw);
        }
        float invs = 1.f / (s + 1e-16f);
        float4 o = make_float4(acc.x * invs, acc.y * invs, acc.z * invs, acc.w * invs);
        *(float4*)(out + (long)ent * 128 + lane * 4) = o;
    }
}

extern "C" void kernel_launch(void* const* d_in, const int* in_sizes, int n_in,
                              void* d_out, int out_size) {
    const float* emb_ent = (const float*)d_in[0];
    const float* emb_rel = (const float*)d_in[1];
    const int*   trip    = (const int*)d_in[2];
    const float* Wa      = (const float*)d_in[3];
    const float* ba      = (const float*)d_in[4];
    const float* av      = (const float*)d_in[5];
    const float* Wg      = (const float*)d_in[6];
    const float* bg      = (const float*)d_in[7];
    float* out = (float*)d_out;

    k_zero<<<(NE + 1 + 255) / 256, 256>>>();
    k_count<<<(NT + 255) / 256, 256>>>(trip);
    k_scan<<<1, 1024>>>();
    k_scatter<<<(NT + 255) / 256, 256>>>(trip);
    k_relgemm<<<NR, 256>>>(emb_rel, Wa, Wg);
    dim3 g((NE + 127) / 128, 3);
    k_entgemm<<<g, 256>>>(emb_ent, Wa, ba, Wg, bg);
    k_main<<<592, 256>>>(av, out);
}

// round 7
// speedup vs baseline: 1.1721x; 1.1682x over previous
#include <cuda_runtime.h>
#include <cuda_bf16.h>
#include <math.h>
#include <cstdint>

#define NE 50000
#define NR 64
#define NT 400000

typedef unsigned long long u64;

// Scratch (static __device__ — no runtime allocation)
__device__ float    g_T[NE * 256];    // [ent][0:128]=emb@Wa2 (head/att), [128:256]=emb@Wg1+bg (head/msg)
__device__ float    g_P1[NE * 128];   // emb@Wa1 + ba (tail/att)
__device__ float    g_RG[NR * 256];   // [rel][0:128]=emb_rel@Wa3, [128:256]=emb_rel@Wg2
__device__ int      g_rowptr[NE + 1];
__device__ int      g_cursor[NE];
__device__ unsigned g_elist[NT];      // head | (rel<<16)
// Pre-transposed bf16 weight images: [group][n][k], group 0=Wa1, 1=Wa2, 2=Wg1
__device__ __align__(16) unsigned short g_Bhi[3 * 16384];
__device__ __align__(16) unsigned short g_Blo[3 * 16384];

// ==================== warp-MMA helpers (sm_80+ PTX, works on sm_103) ====================
__device__ __forceinline__ uint32_t smem_u32(const void* p) {
    uint32_t a;
    asm("{ .reg .u64 t; cvta.to.shared.u64 t, %1; cvt.u32.u64 %0, t; }" : "=r"(a) : "l"(p));
    return a;
}
__device__ __forceinline__ void ldx4(uint32_t r[4], uint32_t addr) {
    asm volatile("ldmatrix.sync.aligned.m8n8.x4.shared.b16 {%0,%1,%2,%3}, [%4];"
                 : "=r"(r[0]), "=r"(r[1]), "=r"(r[2]), "=r"(r[3]) : "r"(addr));
}
__device__ __forceinline__ void ldx2(uint32_t r[2], uint32_t addr) {
    asm volatile("ldmatrix.sync.aligned.m8n8.x2.shared.b16 {%0,%1}, [%2];"
                 : "=r"(r[0]), "=r"(r[1]) : "r"(addr));
}
__device__ __forceinline__ void mma_bf16(float d[4], const uint32_t a[4], const uint32_t b[2]) {
    asm volatile("mma.sync.aligned.m16n8k16.row.col.f32.bf16.bf16.f32 "
                 "{%0,%1,%2,%3}, {%4,%5,%6,%7}, {%8,%9}, {%0,%1,%2,%3};"
                 : "+f"(d[0]), "+f"(d[1]), "+f"(d[2]), "+f"(d[3])
                 : "r"(a[0]), "r"(a[1]), "r"(a[2]), "r"(a[3]), "r"(b[0]), "r"(b[1]));
}
__device__ __forceinline__ float tanh_fast(float x) {
    float y; asm("tanh.approx.f32 %0, %1;" : "=f"(y) : "f"(x)); return y;
}

// ---------------- CSR build ----------------
__global__ void k_zero() {
    int i = blockIdx.x * blockDim.x + threadIdx.x;
    if (i <= NE) g_rowptr[i] = 0;
}

__global__ void k_count(const int* __restrict__ trip) {
    int e = blockIdx.x * blockDim.x + threadIdx.x;
    if (e < NT) atomicAdd(&g_rowptr[trip[3 * e + 2]], 1);
}

__global__ void k_scan() {
    __shared__ int warp_off[32];
    __shared__ int s_carry;
    int tid = threadIdx.x, lane = tid & 31, wid = tid >> 5;
    if (tid == 0) s_carry = 0;
    __syncthreads();
    for (int base = 0; base < NE; base += 1024) {
        int idx = base + tid;
        int v = (idx < NE) ? g_rowptr[idx] : 0;
        int incl = v;
        #pragma unroll
        for (int o = 1; o < 32; o <<= 1) {
            int u = __shfl_up_sync(0xffffffffu, incl, o);
            if (lane >= o) incl += u;
        }
        if (lane == 31) warp_off[wid] = incl;
        __syncthreads();
        if (wid == 0) {
            int w = warp_off[lane];
            int wi = w;
            #pragma unroll
            for (int o = 1; o < 32; o <<= 1) {
                int u = __shfl_up_sync(0xffffffffu, wi, o);
                if (lane >= o) wi += u;
            }
            warp_off[lane] = wi - w;
        }
        __syncthreads();
        int excl = s_carry + warp_off[wid] + (incl - v);
        if (idx < NE) { g_rowptr[idx] = excl; g_cursor[idx] = excl; }
        __syncthreads();
        if (tid == 1023) s_carry = excl + v;
        __syncthreads();
    }
    if (tid == 0) g_rowptr[NE] = s_carry;
}

__global__ void k_scatter(const int* __restrict__ trip) {
    int e = blockIdx.x * blockDim.x + threadIdx.x;
    if (e < NT) {
        int h = trip[3 * e], r = trip[3 * e + 1], t = trip[3 * e + 2];
        int pos = atomicAdd(&g_cursor[t], 1);
        g_elist[pos] = (unsigned)h | ((unsigned)r << 16);
    }
}

// ---------------- weight prep: fp32 -> hi/lo bf16, transposed to [n][k] ----------------
__global__ void k_prepB(const float* __restrict__ Wa, const float* __restrict__ Wg) {
    int idx = blockIdx.x * blockDim.x + threadIdx.x;
    if (idx >= 3 * 16384) return;
    int g = idx >> 14, rem = idx & 16383;
    int n = rem >> 7, k = rem & 127;
    float w = (g == 0) ? Wa[k * 128 + n] : (g == 1) ? Wa[(128 + k) * 128 + n] : Wg[k * 128 + n];
    __nv_bfloat16 hi = __float2bfloat16(w);
    __nv_bfloat16 lo = __float2bfloat16(w - __bfloat162float(hi));
    unsigned short hb, lb;
    memcpy(&hb, &hi, 2); memcpy(&lb, &lo, 2);
    g_Bhi[idx] = hb;
    g_Blo[idx] = lb;
}

// ---------------- tiny relation GEMM (fp32, exact) ----------------
__global__ void k_relgemm(const float* __restrict__ emb_rel,
                          const float* __restrict__ Wa,
                          const float* __restrict__ Wg) {
    __shared__ float er[128];
    int r = blockIdx.x;
    int tid = threadIdx.x;  // 256
    if (tid < 128) er[tid] = emb_rel[r * 128 + tid];
    __syncthreads();
    int j = tid & 127;
    const float* W = (tid < 128) ? (Wa + 256 * 128) : (Wg + 128 * 128);
    float acc = 0.f;
    #pragma unroll 8
    for (int k = 0; k < 128; k++) acc += er[k] * W[k * 128 + j];
    g_RG[r * 256 + tid] = acc;
}

// ---------------- HMMA entity GEMM: block M128 x N128 x K128, bf16 hi/lo 3-pass ----------------
// smem: A_hi[128][136], A_lo, B_hi[128][136] ([n][k]), B_lo — stride 136*2=272B (17x16B: ldmatrix conflict-free)
#define SROW 272
#define SM_A_HI 0
#define SM_A_LO 34816
#define SM_B_HI 69632
#define SM_B_LO 104448
#define SM_TOTAL 139264

__global__ __launch_bounds__(256, 1) void k_mmagemm(const float* __restrict__ A,
                                                    const float* __restrict__ ba,
                                                    const float* __restrict__ bg) {
    extern __shared__ char smem[];
    uint32_t sb = smem_u32(smem);
    int tid = threadIdx.x, wid = tid >> 5, lane = tid & 31;
    int rowBase = blockIdx.x * 128;
    int g = blockIdx.y;
    int warpM = wid & 3, warpN = wid >> 2;  // 4x2 warp grid: 32 rows x 64 cols each

    // ---- fill A (fp32 -> bf16 hi/lo) ----
    for (int i = tid; i < 4096; i += 256) {
        int m = i >> 5, k4 = (i & 31) * 4;
        int gr = rowBase + m;
        float4 v = make_float4(0.f, 0.f, 0.f, 0.f);
        if (gr < NE) v = *(const float4*)(A + (long)gr * 128 + k4);
        __nv_bfloat16 h0 = __float2bfloat16(v.x), h1 = __float2bfloat16(v.y);
        __nv_bfloat16 h2 = __float2bfloat16(v.z), h3 = __float2bfloat16(v.w);
        __nv_bfloat16 l0 = __float2bfloat16(v.x - __bfloat162float(h0));
        __nv_bfloat16 l1 = __float2bfloat16(v.y - __bfloat162float(h1));
        __nv_bfloat16 l2 = __float2bfloat16(v.z - __bfloat162float(h2));
        __nv_bfloat16 l3 = __float2bfloat16(v.w - __bfloat162float(h3));
        int off = m * SROW + k4 * 2;
        __nv_bfloat162 hv0; hv0.x = h0; hv0.y = h1;
        __nv_bfloat162 hv1; hv1.x = h2; hv1.y = h3;
        __nv_bfloat162 lv0; lv0.x = l0; lv0.y = l1;
        __nv_bfloat162 lv1; lv1.x = l2; lv1.y = l3;
        *(__nv_bfloat162*)(smem + SM_A_HI + off) = hv0;
        *(__nv_bfloat162*)(smem + SM_A_HI + off + 4) = hv1;
        *(__nv_bfloat162*)(smem + SM_A_LO + off) = lv0;
        *(__nv_bfloat162*)(smem + SM_A_LO + off + 4) = lv1;
    }
    // ---- fill B (copy pre-transposed hi/lo, add padding) ----
    {
        const uint4* sh = (const uint4*)(g_Bhi + g * 16384);
        const uint4* sl = (const uint4*)(g_Blo + g * 16384);
        for (int i = tid; i < 2048; i += 256) {
            int row = i >> 4, c = i & 15;
            int off = row * SROW + c * 16;
            *(uint4*)(smem + SM_B_HI + off) = sh[i];
            *(uint4*)(smem + SM_B_LO + off) = sl[i];
        }
    }
    __syncthreads();

    float acc[2][8][4];
    #pragma unroll
    for (int mt = 0; mt < 2; mt++)
        #pragma unroll
        for (int nt = 0; nt < 8; nt++)
            #pragma unroll
            for (int j = 0; j < 4; j++) acc[mt][nt][j] = 0.f;

    // ldmatrix base addresses
    uint32_t aAddr = sb + SM_A_HI + (uint32_t)((warpM * 32 + (lane & 15)) * SROW + ((lane >> 4) * 8) * 2);
    uint32_t bAddr = sb + SM_B_HI + (uint32_t)((warpN * 64 + (lane & 7)) * SROW + (((lane >> 3) & 1) * 8) * 2);

    #pragma unroll
    for (int k = 0; k < 8; k++) {
        uint32_t ah[2][4], al[2][4];
        #pragma unroll
        for (int mt = 0; mt < 2; mt++) {
            ldx4(ah[mt], aAddr + mt * (16 * SROW) + k * 32);
            ldx4(al[mt], aAddr + mt * (16 * SROW) + k * 32 + (SM_A_LO - SM_A_HI));
        }
        #pragma unroll
        for (int nt = 0; nt < 8; nt++) {
            uint32_t bh[2], bl[2];
            uint32_t bo = bAddr + nt * (8 * SROW) + k * 32;
            ldx2(bh, bo);
            ldx2(bl, bo + (SM_B_LO - SM_B_HI));
            #pragma unroll
            for (int mt = 0; mt < 2; mt++) {
                mma_bf16(acc[mt][nt], ah[mt], bh);
                mma_bf16(acc[mt][nt], ah[mt], bl);
                mma_bf16(acc[mt][nt], al[mt], bh);
            }
        }
    }

    // ---- epilogue ----
    const float* bias = (g == 0) ? ba : (g == 2) ? bg : nullptr;
    float* base = (g == 0) ? g_P1 : g_T;
    int stride = (g == 0) ? 128 : 256;
    int coff = (g == 2) ? 128 : 0;

    int lrow = lane >> 2, lcol = (lane & 3) * 2;
    #pragma unroll
    for (int mt = 0; mt < 2; mt++) {
        int r0 = rowBase + warpM * 32 + mt * 16 + lrow;
        int r1 = r0 + 8;
        #pragma unroll
        for (int nt = 0; nt < 8; nt++) {
            int n = warpN * 64 + nt * 8 + lcol;
            float b0 = 0.f, b1 = 0.f;
            if (bias) { b0 = __ldg(bias + n); b1 = __ldg(bias + n + 1); }
            if (r0 < NE) {
                float2 v = make_float2(acc[mt][nt][0] + b0, acc[mt][nt][1] + b1);
                *(float2*)(base + (long)r0 * stride + coff + n) = v;
            }
            if (r1 < NE) {
                float2 v = make_float2(acc[mt][nt][2] + b0, acc[mt][nt][3] + b1);
                *(float2*)(base + (long)r1 * stride + coff + n) = v;
            }
        }
    }
}

// ---------------- fused edge kernel: one warp per entity, online softmax ----------------
__global__ __launch_bounds__(256) void k_main(const float* __restrict__ av_g,
                                              float* __restrict__ out) {
    int tid = threadIdx.x, lane = tid & 31, warp = tid >> 5;
    float4 av = ((const float4*)av_g)[lane];
    const float4* RG = (const float4*)g_RG;

    int gw = blockIdx.x * 8 + warp;
    int nw = gridDim.x * 8;
    for (int ent = gw; ent < NE; ent += nw) {
        int beg = g_rowptr[ent], end = g_rowptr[ent + 1];
        float4 p1 = *(const float4*)(g_P1 + (long)ent * 128 + lane * 4);
        float4 sA = make_float4(0.f, 0.f, 0.f, 0.f);
        float4 sG = sA, acc = sA;
        float m = -1e30f, s = 0.f;

        for (int i = beg; i < end; i++) {
            unsigned pk = __ldg(&g_elist[i]);
            int h = pk & 0xFFFFu;
            int r = pk >> 16;
            const float4* T4 = (const float4*)(g_T + (long)h * 256);
            float4 tlo = __ldg(&T4[lane]);
            float4 thi = __ldg(&T4[32 + lane]);
            float4 ra = __ldg(&RG[r * 64 + lane]);
            float4 gr = __ldg(&RG[r * 64 + 32 + lane]);
            sA.x += ra.x; sA.y += ra.y; sA.z += ra.z; sA.w += ra.w;
            sG.x += gr.x; sG.y += gr.y; sG.z += gr.z; sG.w += gr.w;

            float hx = tanh_fast(p1.x + tlo.x + ra.x);
            float hy = tanh_fast(p1.y + tlo.y + ra.y);
            float hz = tanh_fast(p1.z + tlo.z + ra.z);
            float hw = tanh_fast(p1.w + tlo.w + ra.w);
            float part = hx * av.x + hy * av.y + hz * av.z + hw * av.w;
            part += __shfl_xor_sync(0xffffffffu, part, 1);
            part += __shfl_xor_sync(0xffffffffu, part, 2);

            float nm = fmaxf(m, part);
            float f = __expf(m - nm);
            float w = __expf(part - nm);
            s = s * f + w;
            acc.x = acc.x * f + w * (thi.x + gr.x);
            acc.y = acc.y * f + w * (thi.y + gr.y);
            acc.z = acc.z * f + w * (thi.z + gr.z);
            acc.w = acc.w * f + w * (thi.w + gr.w);
            m = nm;
        }
        // self-loop edge
        {
            float inv = (end > beg) ? 1.f / (float)(end - beg) : 1.f;
            const float4* T4 = (const float4*)(g_T + (long)ent * 256);
            float4 tlo = __ldg(&T4[lane]);
            float4 thi = __ldg(&T4[32 + lane]);
            float rax = sA.x * inv, ray = sA.y * inv, raz = sA.z * inv, raw = sA.w * inv;
            float grx = sG.x * inv, gry = sG.y * inv, grz = sG.z * inv, grw = sG.w * inv;

            float hx = tanh_fast(p1.x + tlo.x + rax);
            float hy = tanh_fast(p1.y + tlo.y + ray);
            float hz = tanh_fast(p1.z + tlo.z + raz);
            float hw = tanh_fast(p1.w + tlo.w + raw);
            float part = hx * av.x + hy * av.y + hz * av.z + hw * av.w;
            part += __shfl_xor_sync(0xffffffffu, part, 1);
            part += __shfl_xor_sync(0xffffffffu, part, 2);

            float nm = fmaxf(m, part);
            float f = __expf(m - nm);
            float w = __expf(part - nm);
            s = s * f + w;
            acc.x = acc.x * f + w * (thi.x + grx);
            acc.y = acc.y * f + w * (thi.y + gry);
            acc.z = acc.z * f + w * (thi.z + grz);
            acc.w = acc.w * f + w * (thi.w + grw);
        }
        float invs = 1.f / (s + 1e-16f);
        float4 o = make_float4(acc.x * invs, acc.y * invs, acc.z * invs, acc.w * invs);
        *(float4*)(out + (long)ent * 128 + lane * 4) = o;
    }
}

extern "C" void kernel_launch(void* const* d_in, const int* in_sizes, int n_in,
                              void* d_out, int out_size) {
    const float* emb_ent = (const float*)d_in[0];
    const float* emb_rel = (const float*)d_in[1];
    const int*   trip    = (const int*)d_in[2];
    const float* Wa      = (const float*)d_in[3];
    const float* ba      = (const float*)d_in[4];
    const float* av      = (const float*)d_in[5];
    const float* Wg      = (const float*)d_in[6];
    const float* bg      = (const float*)d_in[7];
    float* out = (float*)d_out;

    static bool attr_set = false;
    if (!attr_set) {
        cudaFuncSetAttribute(k_mmagemm, cudaFuncAttributeMaxDynamicSharedMemorySize, SM_TOTAL);
        attr_set = true;
    }

    k_zero<<<(NE + 1 + 255) / 256, 256>>>();
    k_count<<<(NT + 255) / 256, 256>>>(trip);
    k_scan<<<1, 1024>>>();
    k_scatter<<<(NT + 255) / 256, 256>>>(trip);
    k_prepB<<<(3 * 16384 + 255) / 256, 256>>>(Wa, Wg);
    k_relgemm<<<NR, 256>>>(emb_rel, Wa, Wg);
    dim3 gg((NE + 127) / 128, 3);
    k_mmagemm<<<gg, 256, SM_TOTAL>>>(emb_ent, ba, bg);
    k_main<<<1184, 256>>>(av, out);
}

// round 9
// speedup vs baseline: 1.2692x; 1.0828x over previous
#include <cuda_runtime.h>
#include <cuda_bf16.h>
#include <math.h>
#include <cstdint>

#define NE 50000
#define NR 64
#define NT 400000

typedef unsigned long long u64;

// Scratch (static __device__ — no runtime allocation)
__device__ float    g_T[NE * 256];    // [ent][0:128]=emb@Wa2 (head/att), [128:256]=emb@Wg1+bg (head/msg)
__device__ float    g_P1[NE * 128];   // emb@Wa1 + ba (tail/att)
__device__ float    g_RG[NR * 256];   // [rel][0:128]=emb_rel@Wa3, [128:256]=emb_rel@Wg2
__device__ int      g_rowptr[NE + 1];
__device__ int      g_cursor[NE];
__device__ unsigned g_elist[NT];      // head | (rel<<16)
// Pre-transposed bf16 weight images: [group][n][k], group 0=Wa1, 1=Wa2, 2=Wg1
__device__ __align__(16) unsigned short g_Bhi[3 * 16384];
__device__ __align__(16) unsigned short g_Blo[3 * 16384];

// ==================== warp-MMA helpers (sm_80+ PTX, works on sm_103) ====================
__device__ __forceinline__ uint32_t smem_u32(const void* p) {
    uint32_t a;
    asm("{ .reg .u64 t; cvta.to.shared.u64 t, %1; cvt.u32.u64 %0, t; }" : "=r"(a) : "l"(p));
    return a;
}
__device__ __forceinline__ void ldx4(uint32_t r[4], uint32_t addr) {
    asm volatile("ldmatrix.sync.aligned.m8n8.x4.shared.b16 {%0,%1,%2,%3}, [%4];"
                 : "=r"(r[0]), "=r"(r[1]), "=r"(r[2]), "=r"(r[3]) : "r"(addr));
}
__device__ __forceinline__ void ldx2(uint32_t r[2], uint32_t addr) {
    asm volatile("ldmatrix.sync.aligned.m8n8.x2.shared.b16 {%0,%1}, [%2];"
                 : "=r"(r[0]), "=r"(r[1]) : "r"(addr));
}
__device__ __forceinline__ void mma_bf16(float d[4], const uint32_t a[4], const uint32_t b[2]) {
    asm volatile("mma.sync.aligned.m16n8k16.row.col.f32.bf16.bf16.f32 "
                 "{%0,%1,%2,%3}, {%4,%5,%6,%7}, {%8,%9}, {%0,%1,%2,%3};"
                 : "+f"(d[0]), "+f"(d[1]), "+f"(d[2]), "+f"(d[3])
                 : "r"(a[0]), "r"(a[1]), "r"(a[2]), "r"(a[3]), "r"(b[0]), "r"(b[1]));
}
__device__ __forceinline__ float tanh_fast(float x) {
    float y; asm("tanh.approx.f32 %0, %1;" : "=f"(y) : "f"(x)); return y;
}

// ---------------- CSR build ----------------
__global__ void k_zero() {
    int i = blockIdx.x * blockDim.x + threadIdx.x;
    if (i <= NE) g_rowptr[i] = 0;
}

__global__ void k_count(const int* __restrict__ trip) {
    int e = blockIdx.x * blockDim.x + threadIdx.x;
    if (e < NT) atomicAdd(&g_rowptr[trip[3 * e + 2]], 1);
}

__global__ void k_scan() {
    __shared__ int warp_off[32];
    __shared__ int s_carry;
    int tid = threadIdx.x, lane = tid & 31, wid = tid >> 5;
    if (tid == 0) s_carry = 0;
    __syncthreads();
    for (int base = 0; base < NE; base += 1024) {
        int idx = base + tid;
        int v = (idx < NE) ? g_rowptr[idx] : 0;
        int incl = v;
        #pragma unroll
        for (int o = 1; o < 32; o <<= 1) {
            int u = __shfl_up_sync(0xffffffffu, incl, o);
            if (lane >= o) incl += u;
        }
        if (lane == 31) warp_off[wid] = incl;
        __syncthreads();
        if (wid == 0) {
            int w = warp_off[lane];
            int wi = w;
            #pragma unroll
            for (int o = 1; o < 32; o <<= 1) {
                int u = __shfl_up_sync(0xffffffffu, wi, o);
                if (lane >= o) wi += u;
            }
            warp_off[lane] = wi - w;
        }
        __syncthreads();
        int excl = s_carry + warp_off[wid] + (incl - v);
        if (idx < NE) { g_rowptr[idx] = excl; g_cursor[idx] = excl; }
        __syncthreads();
        if (tid == 1023) s_carry = excl + v;
        __syncthreads();
    }
    if (tid == 0) g_rowptr[NE] = s_carry;
}

__global__ void k_scatter(const int* __restrict__ trip) {
    int e = blockIdx.x * blockDim.x + threadIdx.x;
    if (e < NT) {
        int h = trip[3 * e], r = trip[3 * e + 1], t = trip[3 * e + 2];
        int pos = atomicAdd(&g_cursor[t], 1);
        g_elist[pos] = (unsigned)h | ((unsigned)r << 16);
    }
}

// ---------------- weight prep: fp32 -> hi/lo bf16, transposed to [n][k] ----------------
__global__ void k_prepB(const float* __restrict__ Wa, const float* __restrict__ Wg) {
    int idx = blockIdx.x * blockDim.x + threadIdx.x;
    if (idx >= 3 * 16384) return;
    int g = idx >> 14, rem = idx & 16383;
    int n = rem >> 7, k = rem & 127;
    float w = (g == 0) ? Wa[k * 128 + n] : (g == 1) ? Wa[(128 + k) * 128 + n] : Wg[k * 128 + n];
    __nv_bfloat16 hi = __float2bfloat16(w);
    __nv_bfloat16 lo = __float2bfloat16(w - __bfloat162float(hi));
    unsigned short hb, lb;
    memcpy(&hb, &hi, 2); memcpy(&lb, &lo, 2);
    g_Bhi[idx] = hb;
    g_Blo[idx] = lb;
}

// ---------------- tiny relation GEMM (fp32, exact) ----------------
__global__ void k_relgemm(const float* __restrict__ emb_rel,
                          const float* __restrict__ Wa,
                          const float* __restrict__ Wg) {
    __shared__ float er[128];
    int r = blockIdx.x;
    int tid = threadIdx.x;  // 256
    if (tid < 128) er[tid] = emb_rel[r * 128 + tid];
    __syncthreads();
    int j = tid & 127;
    const float* W = (tid < 128) ? (Wa + 256 * 128) : (Wg + 128 * 128);
    float acc = 0.f;
    #pragma unroll 8
    for (int k = 0; k < 128; k++) acc += er[k] * W[k * 128 + j];
    g_RG[r * 256 + tid] = acc;
}

// ---------------- HMMA entity GEMM: block M128 x (3 x N128) x K128, bf16 hi/lo 3-pass ----------------
// A loaded/converted ONCE, the 3 weight groups looped with B-reload only.
// smem: A_hi[128][136], A_lo, B_hi[128][136] ([n][k]), B_lo — stride 272B (17x16B: ldmatrix conflict-free)
#define SROW 272
#define SM_A_HI 0
#define SM_A_LO 34816
#define SM_B_HI 69632
#define SM_B_LO 104448
#define SM_TOTAL 139264

__global__ __launch_bounds__(256, 1) void k_mmagemm(const float* __restrict__ A,
                                                    const float* __restrict__ ba,
                                                    const float* __restrict__ bg) {
    extern __shared__ char smem[];
    uint32_t sb = smem_u32(smem);
    int tid = threadIdx.x, wid = tid >> 5, lane = tid & 31;
    int rowBase = blockIdx.x * 128;
    int warpM = wid & 3, warpN = wid >> 2;  // 4x2 warp grid: 32 rows x 64 cols each

    // ---- fill A once (fp32 -> bf16 hi/lo) ----
    for (int i = tid; i < 4096; i += 256) {
        int m = i >> 5, k4 = (i & 31) * 4;
        int gr = rowBase + m;
        float4 v = make_float4(0.f, 0.f, 0.f, 0.f);
        if (gr < NE) v = *(const float4*)(A + (long)gr * 128 + k4);
        __nv_bfloat16 h0 = __float2bfloat16(v.x), h1 = __float2bfloat16(v.y);
        __nv_bfloat16 h2 = __float2bfloat16(v.z), h3 = __float2bfloat16(v.w);
        __nv_bfloat16 l0 = __float2bfloat16(v.x - __bfloat162float(h0));
        __nv_bfloat16 l1 = __float2bfloat16(v.y - __bfloat162float(h1));
        __nv_bfloat16 l2 = __float2bfloat16(v.z - __bfloat162float(h2));
        __nv_bfloat16 l3 = __float2bfloat16(v.w - __bfloat162float(h3));
        int off = m * SROW + k4 * 2;
        __nv_bfloat162 hv0; hv0.x = h0; hv0.y = h1;
        __nv_bfloat162 hv1; hv1.x = h2; hv1.y = h3;
        __nv_bfloat162 lv0; lv0.x = l0; lv0.y = l1;
        __nv_bfloat162 lv1; lv1.x = l2; lv1.y = l3;
        *(__nv_bfloat162*)(smem + SM_A_HI + off) = hv0;
        *(__nv_bfloat162*)(smem + SM_A_HI + off + 4) = hv1;
        *(__nv_bfloat162*)(smem + SM_A_LO + off) = lv0;
        *(__nv_bfloat162*)(smem + SM_A_LO + off + 4) = lv1;
    }

    uint32_t aAddr = sb + SM_A_HI + (uint32_t)((warpM * 32 + (lane & 15)) * SROW + ((lane >> 4) * 8) * 2);
    uint32_t bAddr = sb + SM_B_HI + (uint32_t)((warpN * 64 + (lane & 7)) * SROW + (((lane >> 3) & 1) * 8) * 2);

    int lrow = lane >> 2, lcol = (lane & 3) * 2;

    for (int g = 0; g < 3; g++) {
        // ---- fill B for this group (prev group's MMAs all done: sync below covers) ----
        {
            const uint4* sh = (const uint4*)(g_Bhi + g * 16384);
            const uint4* sl = (const uint4*)(g_Blo + g * 16384);
            for (int i = tid; i < 2048; i += 256) {
                int row = i >> 4, c = i & 15;
                int off = row * SROW + c * 16;
                *(uint4*)(smem + SM_B_HI + off) = sh[i];
                *(uint4*)(smem + SM_B_LO + off) = sl[i];
            }
        }
        __syncthreads();

        float acc[2][8][4];
        #pragma unroll
        for (int mt = 0; mt < 2; mt++)
            #pragma unroll
            for (int nt = 0; nt < 8; nt++)
                #pragma unroll
                for (int j = 0; j < 4; j++) acc[mt][nt][j] = 0.f;

        #pragma unroll
        for (int k = 0; k < 8; k++) {
            uint32_t ah[2][4], al[2][4];
            #pragma unroll
            for (int mt = 0; mt < 2; mt++) {
                ldx4(ah[mt], aAddr + mt * (16 * SROW) + k * 32);
                ldx4(al[mt], aAddr + mt * (16 * SROW) + k * 32 + (SM_A_LO - SM_A_HI));
            }
            #pragma unroll
            for (int nt = 0; nt < 8; nt++) {
                uint32_t bh[2], bl[2];
                uint32_t bo = bAddr + nt * (8 * SROW) + k * 32;
                ldx2(bh, bo);
                ldx2(bl, bo + (SM_B_LO - SM_B_HI));
                #pragma unroll
                for (int mt = 0; mt < 2; mt++) {
                    mma_bf16(acc[mt][nt], ah[mt], bh);
                    mma_bf16(acc[mt][nt], ah[mt], bl);
                    mma_bf16(acc[mt][nt], al[mt], bh);
                }
            }
        }
        __syncthreads();  // all warps done reading B before next-group overwrite

        // ---- epilogue for this group ----
        const float* bias = (g == 0) ? ba : (g == 2) ? bg : nullptr;
        float* base = (g == 0) ? g_P1 : g_T;
        int stride = (g == 0) ? 128 : 256;
        int coff = (g == 2) ? 128 : 0;

        #pragma unroll
        for (int mt = 0; mt < 2; mt++) {
            int r0 = rowBase + warpM * 32 + mt * 16 + lrow;
            int r1 = r0 + 8;
            #pragma unroll
            for (int nt = 0; nt < 8; nt++) {
                int n = warpN * 64 + nt * 8 + lcol;
                float b0 = 0.f, b1 = 0.f;
                if (bias) { b0 = __ldg(bias + n); b1 = __ldg(bias + n + 1); }
                if (r0 < NE) {
                    float2 v = make_float2(acc[mt][nt][0] + b0, acc[mt][nt][1] + b1);
                    *(float2*)(base + (long)r0 * stride + coff + n) = v;
                }
                if (r1 < NE) {
                    float2 v = make_float2(acc[mt][nt][2] + b0, acc[mt][nt][3] + b1);
                    *(float2*)(base + (long)r1 * stride + coff + n) = v;
                }
            }
        }
    }
}

// ---------------- fused edge kernel: one warp per entity, online softmax, SW pipeline ----------------
__global__ __launch_bounds__(256) void k_main(const float* __restrict__ av_g,
                                              float* __restrict__ out) {
    int tid = threadIdx.x, lane = tid & 31, warp = tid >> 5;
    float4 av = ((const float4*)av_g)[lane];
    const float4* RG = (const float4*)g_RG;

    int gw = blockIdx.x * 8 + warp;
    int nw = gridDim.x * 8;
    for (int ent = gw; ent < NE; ent += nw) {
        int beg = g_rowptr[ent], end = g_rowptr[ent + 1];
        float4 p1 = *(const float4*)(g_P1 + (long)ent * 128 + lane * 4);
        float4 sA = make_float4(0.f, 0.f, 0.f, 0.f);
        float4 sG = sA, acc = sA;
        float m = -1e30f, s = 0.f;

        // pipeline registers (next-edge data)
        float4 ntlo, nthi, nra, ngr;
        if (beg < end) {
            unsigned pk = __ldg(&g_elist[beg]);
            int h = pk & 0xFFFFu, r = pk >> 16;
            const float4* T4 = (const float4*)(g_T + (long)h * 256);
            ntlo = __ldg(&T4[lane]);
            nthi = __ldg(&T4[32 + lane]);
            nra  = __ldg(&RG[r * 64 + lane]);
            ngr  = __ldg(&RG[r * 64 + 32 + lane]);
        }

        for (int i = beg; i < end; i++) {
            float4 tlo = ntlo, thi = nthi, ra = nra, gr = ngr;
            if (i + 1 < end) {  // issue next-edge gathers before the serial chain
                unsigned pk = __ldg(&g_elist[i + 1]);
                int h = pk & 0xFFFFu, r = pk >> 16;
                const float4* T4 = (const float4*)(g_T + (long)h * 256);
                ntlo = __ldg(&T4[lane]);
                nthi = __ldg(&T4[32 + lane]);
                nra  = __ldg(&RG[r * 64 + lane]);
                ngr  = __ldg(&RG[r * 64 + 32 + lane]);
            }
            sA.x += ra.x; sA.y += ra.y; sA.z += ra.z; sA.w += ra.w;
            sG.x += gr.x; sG.y += gr.y; sG.z += gr.z; sG.w += gr.w;

            float hx = tanh_fast(p1.x + tlo.x + ra.x);
            float hy = tanh_fast(p1.y + tlo.y + ra.y);
            float hz = tanh_fast(p1.z + tlo.z + ra.z);
            float hw = tanh_fast(p1.w + tlo.w + ra.w);
            float part = hx * av.x + hy * av.y + hz * av.z + hw * av.w;
            part += __shfl_xor_sync(0xffffffffu, part, 1);
            part += __shfl_xor_sync(0xffffffffu, part, 2);

            float nm = fmaxf(m, part);
            float f = __expf(m - nm);
            float w = __expf(part - nm);
            s = s * f + w;
            acc.x = acc.x * f + w * (thi.x + gr.x);
            acc.y = acc.y * f + w * (thi.y + gr.y);
            acc.z = acc.z * f + w * (thi.z + gr.z);
            acc.w = acc.w * f + w * (thi.w + gr.w);
            m = nm;
        }
        // self-loop edge
        {
            float inv = (end > beg) ? 1.f / (float)(end - beg) : 1.f;
            const float4* T4 = (const float4*)(g_T + (long)ent * 256);
            float4 tlo = __ldg(&T4[lane]);
            float4 thi = __ldg(&T4[32 + lane]);
            float rax = sA.x * inv, ray = sA.y * inv, raz = sA.z * inv, raw = sA.w * inv;
            float grx = sG.x * inv, gry = sG.y * inv, grz = sG.z * inv, grw = sG.w * inv;

            float hx = tanh_fast(p1.x + tlo.x + rax);
            float hy = tanh_fast(p1.y + tlo.y + ray);
            float hz = tanh_fast(p1.z + tlo.z + raz);
            float hw = tanh_fast(p1.w + tlo.w + raw);
            float part = hx * av.x + hy * av.y + hz * av.z + hw * av.w;
            part += __shfl_xor_sync(0xffffffffu, part, 1);
            part += __shfl_xor_sync(0xffffffffu, part, 2);

            float nm = fmaxf(m, part);
            float f = __expf(m - nm);
            float w = __expf(part - nm);
            s = s * f + w;
            acc.x = acc.x * f + w * (thi.x + grx);
            acc.y = acc.y * f + w * (thi.y + gry);
            acc.z = acc.z * f + w * (thi.z + grz);
            acc.w = acc.w * f + w * (thi.w + grw);
        }
        float invs = 1.f / (s + 1e-16f);
        float4 o = make_float4(acc.x * invs, acc.y * invs, acc.z * invs, acc.w * invs);
        *(float4*)(out + (long)ent * 128 + lane * 4) = o;
    }
}

extern "C" void kernel_launch(void* const* d_in, const int* in_sizes, int n_in,
                              void* d_out, int out_size) {
    const float* emb_ent = (const float*)d_in[0];
    const float* emb_rel = (const float*)d_in[1];
    const int*   trip    = (const int*)d_in[2];
    const float* Wa      = (const float*)d_in[3];
    const float* ba      = (const float*)d_in[4];
    const float* av      = (const float*)d_in[5];
    const float* Wg      = (const float*)d_in[6];
    const float* bg      = (const float*)d_in[7];
    float* out = (float*)d_out;

    static bool attr_set = false;
    if (!attr_set) {
        cudaFuncSetAttribute(k_mmagemm, cudaFuncAttributeMaxDynamicSharedMemorySize, SM_TOTAL);
        attr_set = true;
    }

    k_zero<<<(NE + 1 + 255) / 256, 256>>>();
    k_count<<<(NT + 255) / 256, 256>>>(trip);
    k_scan<<<1, 1024>>>();
    k_scatter<<<(NT + 255) / 256, 256>>>(trip);
    k_prepB<<<(3 * 16384 + 255) / 256, 256>>>(Wa, Wg);
    k_relgemm<<<NR, 256>>>(emb_rel, Wa, Wg);
    k_mmagemm<<<(NE + 127) / 128, 256, SM_TOTAL>>>(emb_ent, ba, bg);
    k_main<<<1184, 256>>>(av, out);
}

// round 10
// speedup vs baseline: 1.4446x; 1.1382x over previous
#include <cuda_runtime.h>
#include <cuda_bf16.h>
#include <math.h>
#include <cstdint>

#define NE 50000
#define NR 64
#define NT 400000

typedef unsigned long long u64;

// Scratch (static __device__ — no runtime allocation)
__device__ float    g_T[NE * 256];    // [ent][0:128]=emb@Wa2 (head/att), [128:256]=emb@Wg1+bg (head/msg)
__device__ float    g_P1[NE * 128];   // emb@Wa1 + ba (tail/att)
__device__ float    g_RG[NR * 256];   // [rel][0:128]=emb_rel@Wa3, [128:256]=emb_rel@Wg2
__device__ int      g_rowptr[NE + 1];
__device__ int      g_cursor[NE];
__device__ unsigned g_elist[NT];      // head | (rel<<16)
__device__ int      g_bsum[128];
__device__ int      g_boff[128];
// Pre-transposed bf16 weight images: [group][n][k], group 0=Wa1, 1=Wa2, 2=Wg1
__device__ __align__(16) unsigned short g_Bhi[3 * 16384];
__device__ __align__(16) unsigned short g_Blo[3 * 16384];

// ==================== warp-MMA helpers (sm_80+ PTX, works on sm_103) ====================
__device__ __forceinline__ uint32_t smem_u32(const void* p) {
    uint32_t a;
    asm("{ .reg .u64 t; cvta.to.shared.u64 t, %1; cvt.u32.u64 %0, t; }" : "=r"(a) : "l"(p));
    return a;
}
__device__ __forceinline__ void ldx4(uint32_t r[4], uint32_t addr) {
    asm volatile("ldmatrix.sync.aligned.m8n8.x4.shared.b16 {%0,%1,%2,%3}, [%4];"
                 : "=r"(r[0]), "=r"(r[1]), "=r"(r[2]), "=r"(r[3]) : "r"(addr));
}
__device__ __forceinline__ void ldx2(uint32_t r[2], uint32_t addr) {
    asm volatile("ldmatrix.sync.aligned.m8n8.x2.shared.b16 {%0,%1}, [%2];"
                 : "=r"(r[0]), "=r"(r[1]) : "r"(addr));
}
__device__ __forceinline__ void mma_bf16(float d[4], const uint32_t a[4], const uint32_t b[2]) {
    asm volatile("mma.sync.aligned.m16n8k16.row.col.f32.bf16.bf16.f32 "
                 "{%0,%1,%2,%3}, {%4,%5,%6,%7}, {%8,%9}, {%0,%1,%2,%3};"
                 : "+f"(d[0]), "+f"(d[1]), "+f"(d[2]), "+f"(d[3])
                 : "r"(a[0]), "r"(a[1]), "r"(a[2]), "r"(a[3]), "r"(b[0]), "r"(b[1]));
}
__device__ __forceinline__ float tanh_fast(float x) {
    float y; asm("tanh.approx.f32 %0, %1;" : "=f"(y) : "f"(x)); return y;
}

// ---------------- CSR build ----------------
__global__ void k_zero() {
    int i = blockIdx.x * blockDim.x + threadIdx.x;
    if (i <= NE) g_rowptr[i] = 0;
}

__global__ void k_count(const int* __restrict__ trip) {
    int e = blockIdx.x * blockDim.x + threadIdx.x;
    if (e < NT) atomicAdd(&g_rowptr[trip[3 * e + 2]], 1);
}

// 3-stage parallel scan: per-block sums -> scan of 98 sums -> per-block prefix
#define SCB 512
#define NSCB ((NE + SCB - 1) / SCB)   // 98

__global__ void k_scanA() {
    __shared__ int wsum[16];
    int b = blockIdx.x, t = threadIdx.x, lane = t & 31, w = t >> 5;
    int idx = b * SCB + t;
    int v = (idx < NE) ? g_rowptr[idx] : 0;
    #pragma unroll
    for (int o = 16; o > 0; o >>= 1) v += __shfl_down_sync(0xffffffffu, v, o);
    if (lane == 0) wsum[w] = v;
    __syncthreads();
    if (t == 0) {
        int s = 0;
        #pragma unroll
        for (int i = 0; i < 16; i++) s += wsum[i];
        g_bsum[b] = s;
    }
}

__global__ void k_scanB() {  // 1 block, 128 threads: exclusive scan of NSCB block sums
    __shared__ int woff[4];
    int t = threadIdx.x, lane = t & 31, w = t >> 5;
    int v = (t < NSCB) ? g_bsum[t] : 0;
    int incl = v;
    #pragma unroll
    for (int o = 1; o < 32; o <<= 1) {
        int u = __shfl_up_sync(0xffffffffu, incl, o);
        if (lane >= o) incl += u;
    }
    if (lane == 31) woff[w] = incl;
    __syncthreads();
    int base = 0;
    for (int i = 0; i < w; i++) base += woff[i];
    if (t < NSCB) g_boff[t] = base + incl - v;
    if (t == 0) g_rowptr[NE] = NT;
}

__global__ void k_scanC() {
    __shared__ int wsum[16];
    int b = blockIdx.x, t = threadIdx.x, lane = t & 31, w = t >> 5;
    int idx = b * SCB + t;
    int v = (idx < NE) ? g_rowptr[idx] : 0;
    int incl = v;
    #pragma unroll
    for (int o = 1; o < 32; o <<= 1) {
        int u = __shfl_up_sync(0xffffffffu, incl, o);
        if (lane >= o) incl += u;
    }
    if (lane == 31) wsum[w] = incl;
    __syncthreads();
    if (w == 0 && lane < 16) {
        int x = wsum[lane];
        #pragma unroll
        for (int o = 1; o < 16; o <<= 1) {
            int u = __shfl_up_sync(0xffffu, x, o);
            if (lane >= o) x += u;
        }
        wsum[lane] = x;  // inclusive
    }
    __syncthreads();
    int excl = g_boff[b] + (w > 0 ? wsum[w - 1] : 0) + (incl - v);
    if (idx < NE) { g_rowptr[idx] = excl; g_cursor[idx] = excl; }
}

__global__ void k_scatter(const int* __restrict__ trip) {
    int e = blockIdx.x * blockDim.x + threadIdx.x;
    if (e < NT) {
        int h = trip[3 * e], r = trip[3 * e + 1], t = trip[3 * e + 2];
        int pos = atomicAdd(&g_cursor[t], 1);
        g_elist[pos] = (unsigned)h | ((unsigned)r << 16);
    }
}

// ---------------- weight prep: fp32 -> hi/lo bf16, transposed to [n][k] ----------------
__global__ void k_prepB(const float* __restrict__ Wa, const float* __restrict__ Wg) {
    int idx = blockIdx.x * blockDim.x + threadIdx.x;
    if (idx >= 3 * 16384) return;
    int g = idx >> 14, rem = idx & 16383;
    int n = rem >> 7, k = rem & 127;
    float w = (g == 0) ? Wa[k * 128 + n] : (g == 1) ? Wa[(128 + k) * 128 + n] : Wg[k * 128 + n];
    __nv_bfloat16 hi = __float2bfloat16(w);
    __nv_bfloat16 lo = __float2bfloat16(w - __bfloat162float(hi));
    unsigned short hb, lb;
    memcpy(&hb, &hi, 2); memcpy(&lb, &lo, 2);
    g_Bhi[idx] = hb;
    g_Blo[idx] = lb;
}

// ---------------- tiny relation GEMM (fp32, exact) ----------------
__global__ void k_relgemm(const float* __restrict__ emb_rel,
                          const float* __restrict__ Wa,
                          const float* __restrict__ Wg) {
    __shared__ float er[128];
    int r = blockIdx.x;
    int tid = threadIdx.x;  // 256
    if (tid < 128) er[tid] = emb_rel[r * 128 + tid];
    __syncthreads();
    int j = tid & 127;
    const float* W = (tid < 128) ? (Wa + 256 * 128) : (Wg + 128 * 128);
    float acc = 0.f;
    #pragma unroll 8
    for (int k = 0; k < 128; k++) acc += er[k] * W[k * 128 + j];
    g_RG[r * 256 + tid] = acc;
}

// ---------------- HMMA entity GEMM: block M128 x (3 x N128) x K128, bf16 hi/lo 3-pass ----------------
#define SROW 272
#define SM_A_HI 0
#define SM_A_LO 34816
#define SM_B_HI 69632
#define SM_B_LO 104448
#define SM_TOTAL 139264

__global__ __launch_bounds__(256, 1) void k_mmagemm(const float* __restrict__ A,
                                                    const float* __restrict__ ba,
                                                    const float* __restrict__ bg) {
    extern __shared__ char smem[];
    uint32_t sb = smem_u32(smem);
    int tid = threadIdx.x, wid = tid >> 5, lane = tid & 31;
    int rowBase = blockIdx.x * 128;
    int warpM = wid & 3, warpN = wid >> 2;

    // ---- fill A once (fp32 -> bf16 hi/lo) ----
    for (int i = tid; i < 4096; i += 256) {
        int m = i >> 5, k4 = (i & 31) * 4;
        int gr = rowBase + m;
        float4 v = make_float4(0.f, 0.f, 0.f, 0.f);
        if (gr < NE) v = *(const float4*)(A + (long)gr * 128 + k4);
        __nv_bfloat16 h0 = __float2bfloat16(v.x), h1 = __float2bfloat16(v.y);
        __nv_bfloat16 h2 = __float2bfloat16(v.z), h3 = __float2bfloat16(v.w);
        __nv_bfloat16 l0 = __float2bfloat16(v.x - __bfloat162float(h0));
        __nv_bfloat16 l1 = __float2bfloat16(v.y - __bfloat162float(h1));
        __nv_bfloat16 l2 = __float2bfloat16(v.z - __bfloat162float(h2));
        __nv_bfloat16 l3 = __float2bfloat16(v.w - __bfloat162float(h3));
        int off = m * SROW + k4 * 2;
        __nv_bfloat162 hv0; hv0.x = h0; hv0.y = h1;
        __nv_bfloat162 hv1; hv1.x = h2; hv1.y = h3;
        __nv_bfloat162 lv0; lv0.x = l0; lv0.y = l1;
        __nv_bfloat162 lv1; lv1.x = l2; lv1.y = l3;
        *(__nv_bfloat162*)(smem + SM_A_HI + off) = hv0;
        *(__nv_bfloat162*)(smem + SM_A_HI + off + 4) = hv1;
        *(__nv_bfloat162*)(smem + SM_A_LO + off) = lv0;
        *(__nv_bfloat162*)(smem + SM_A_LO + off + 4) = lv1;
    }

    uint32_t aAddr = sb + SM_A_HI + (uint32_t)((warpM * 32 + (lane & 15)) * SROW + ((lane >> 4) * 8) * 2);
    uint32_t bAddr = sb + SM_B_HI + (uint32_t)((warpN * 64 + (lane & 7)) * SROW + (((lane >> 3) & 1) * 8) * 2);

    int lrow = lane >> 2, lcol = (lane & 3) * 2;

    for (int g = 0; g < 3; g++) {
        {
            const uint4* sh = (const uint4*)(g_Bhi + g * 16384);
            const uint4* sl = (const uint4*)(g_Blo + g * 16384);
            for (int i = tid; i < 2048; i += 256) {
                int row = i >> 4, c = i & 15;
                int off = row * SROW + c * 16;
                *(uint4*)(smem + SM_B_HI + off) = sh[i];
                *(uint4*)(smem + SM_B_LO + off) = sl[i];
            }
        }
        __syncthreads();

        float acc[2][8][4];
        #pragma unroll
        for (int mt = 0; mt < 2; mt++)
            #pragma unroll
            for (int nt = 0; nt < 8; nt++)
                #pragma unroll
                for (int j = 0; j < 4; j++) acc[mt][nt][j] = 0.f;

        #pragma unroll
        for (int k = 0; k < 8; k++) {
            uint32_t ah[2][4], al[2][4];
            #pragma unroll
            for (int mt = 0; mt < 2; mt++) {
                ldx4(ah[mt], aAddr + mt * (16 * SROW) + k * 32);
                ldx4(al[mt], aAddr + mt * (16 * SROW) + k * 32 + (SM_A_LO - SM_A_HI));
            }
            #pragma unroll
            for (int nt = 0; nt < 8; nt++) {
                uint32_t bh[2], bl[2];
                uint32_t bo = bAddr + nt * (8 * SROW) + k * 32;
                ldx2(bh, bo);
                ldx2(bl, bo + (SM_B_LO - SM_B_HI));
                #pragma unroll
                for (int mt = 0; mt < 2; mt++) {
                    mma_bf16(acc[mt][nt], ah[mt], bh);
                    mma_bf16(acc[mt][nt], ah[mt], bl);
                    mma_bf16(acc[mt][nt], al[mt], bh);
                }
            }
        }
        __syncthreads();

        const float* bias = (g == 0) ? ba : (g == 2) ? bg : nullptr;
        float* base = (g == 0) ? g_P1 : g_T;
        int stride = (g == 0) ? 128 : 256;
        int coff = (g == 2) ? 128 : 0;

        #pragma unroll
        for (int mt = 0; mt < 2; mt++) {
            int r0 = rowBase + warpM * 32 + mt * 16 + lrow;
            int r1 = r0 + 8;
            #pragma unroll
            for (int nt = 0; nt < 8; nt++) {
                int n = warpN * 64 + nt * 8 + lcol;
                float b0 = 0.f, b1 = 0.f;
                if (bias) { b0 = __ldg(bias + n); b1 = __ldg(bias + n + 1); }
                if (r0 < NE) {
                    float2 v = make_float2(acc[mt][nt][0] + b0, acc[mt][nt][1] + b1);
                    *(float2*)(base + (long)r0 * stride + coff + n) = v;
                }
                if (r1 < NE) {
                    float2 v = make_float2(acc[mt][nt][2] + b0, acc[mt][nt][3] + b1);
                    *(float2*)(base + (long)r1 * stride + coff + n) = v;
                }
            }
        }
    }
}

// ---------------- fused edge kernel: pair-pipelined online softmax ----------------
struct Edge { float4 tlo, thi, ra, gr; };

__device__ __forceinline__ void fetch_edge(int idx, int lane, const float4* RG, Edge& E) {
    unsigned pk = __ldg(&g_elist[idx]);
    int h = pk & 0xFFFFu, r = pk >> 16;
    const float4* T4 = (const float4*)(g_T + (long)h * 256);
    E.tlo = __ldg(&T4[lane]);
    E.thi = __ldg(&T4[32 + lane]);
    E.ra  = __ldg(&RG[r * 64 + lane]);
    E.gr  = __ldg(&RG[r * 64 + 32 + lane]);
}

__device__ __forceinline__ void consume(const Edge& E, const float4& p1, const float4& av,
                                        float4& sA, float4& sG, float4& acc, float& m, float& s) {
    sA.x += E.ra.x; sA.y += E.ra.y; sA.z += E.ra.z; sA.w += E.ra.w;
    sG.x += E.gr.x; sG.y += E.gr.y; sG.z += E.gr.z; sG.w += E.gr.w;
    float hx = tanh_fast(p1.x + E.tlo.x + E.ra.x);
    float hy = tanh_fast(p1.y + E.tlo.y + E.ra.y);
    float hz = tanh_fast(p1.z + E.tlo.z + E.ra.z);
    float hw = tanh_fast(p1.w + E.tlo.w + E.ra.w);
    float part = hx * av.x + hy * av.y + hz * av.z + hw * av.w;
    part += __shfl_xor_sync(0xffffffffu, part, 1);
    part += __shfl_xor_sync(0xffffffffu, part, 2);
    float nm = fmaxf(m, part);
    float f = __expf(m - nm);
    float w = __expf(part - nm);
    s = s * f + w;
    acc.x = acc.x * f + w * (E.thi.x + E.gr.x);
    acc.y = acc.y * f + w * (E.thi.y + E.gr.y);
    acc.z = acc.z * f + w * (E.thi.z + E.gr.z);
    acc.w = acc.w * f + w * (E.thi.w + E.gr.w);
    m = nm;
}

__global__ __launch_bounds__(256) void k_main(const float* __restrict__ av_g,
                                              float* __restrict__ out) {
    int tid = threadIdx.x, lane = tid & 31, warp = tid >> 5;
    float4 av = ((const float4*)av_g)[lane];
    const float4* RG = (const float4*)g_RG;

    int gw = blockIdx.x * 8 + warp;
    int nw = gridDim.x * 8;
    for (int ent = gw; ent < NE; ent += nw) {
        int beg = g_rowptr[ent], end = g_rowptr[ent + 1];
        float4 p1 = *(const float4*)(g_P1 + (long)ent * 128 + lane * 4);
        float4 sA = make_float4(0.f, 0.f, 0.f, 0.f);
        float4 sG = sA, acc = sA;
        float m = -1e30f, s = 0.f;

        int deg = end - beg;
        int end2 = beg + (deg & ~1);  // paired portion

        Edge E0, E1;
        if (beg < end2) { fetch_edge(beg, lane, RG, E0); fetch_edge(beg + 1, lane, RG, E1); }
        for (int i = beg; i < end2; i += 2) {
            Edge C0 = E0, C1 = E1;
            if (i + 3 < end2 + 1) {  // i+2 < end2 (paired -> i+3 valid too)
                fetch_edge(i + 2, lane, RG, E0);
                fetch_edge(i + 3, lane, RG, E1);
            }
            consume(C0, p1, av, sA, sG, acc, m, s);
            consume(C1, p1, av, sA, sG, acc, m, s);
        }
        if (end2 < end) {  // odd tail edge
            Edge Et;
            fetch_edge(end2, lane, RG, Et);
            consume(Et, p1, av, sA, sG, acc, m, s);
        }

        // self-loop edge: rel term = (sum Ra[rel]) / freq
        {
            float inv = (deg > 0) ? 1.f / (float)deg : 1.f;
            Edge Es;
            const float4* T4 = (const float4*)(g_T + (long)ent * 256);
            Es.tlo = __ldg(&T4[lane]);
            Es.thi = __ldg(&T4[32 + lane]);
            Es.ra = make_float4(sA.x * inv, sA.y * inv, sA.z * inv, sA.w * inv);
            Es.gr = make_float4(sG.x * inv, sG.y * inv, sG.z * inv, sG.w * inv);
            float4 dummyA = make_float4(0, 0, 0, 0), dummyG = dummyA;
            consume(Es, p1, av, dummyA, dummyG, acc, m, s);
        }
        float invs = 1.f / (s + 1e-16f);
        float4 o = make_float4(acc.x * invs, acc.y * invs, acc.z * invs, acc.w * invs);
        *(float4*)(out + (long)ent * 128 + lane * 4) = o;
    }
}

extern "C" void kernel_launch(void* const* d_in, const int* in_sizes, int n_in,
                              void* d_out, int out_size) {
    const float* emb_ent = (const float*)d_in[0];
    const float* emb_rel = (const float*)d_in[1];
    const int*   trip    = (const int*)d_in[2];
    const float* Wa      = (const float*)d_in[3];
    const float* ba      = (const float*)d_in[4];
    const float* av      = (const float*)d_in[5];
    const float* Wg      = (const float*)d_in[6];
    const float* bg      = (const float*)d_in[7];
    float* out = (float*)d_out;

    static cudaStream_t s2 = nullptr;
    static cudaEvent_t evFork = nullptr, evJoin = nullptr;
    if (!s2) {
        cudaStreamCreateWithFlags(&s2, cudaStreamNonBlocking);
        cudaEventCreateWithFlags(&evFork, cudaEventDisableTiming);
        cudaEventCreateWithFlags(&evJoin, cudaEventDisableTiming);
        cudaFuncSetAttribute(k_mmagemm, cudaFuncAttributeMaxDynamicSharedMemorySize, SM_TOTAL);
    }

    // fork: CSR chain on s2, GEMM chain on default stream, join before k_main
    cudaEventRecord(evFork, 0);
    cudaStreamWaitEvent(s2, evFork, 0);

    // --- CSR chain (s2) ---
    k_zero<<<(NE + 1 + 255) / 256, 256, 0, s2>>>();
    k_count<<<(NT + 255) / 256, 256, 0, s2>>>(trip);
    k_scanA<<<NSCB, SCB, 0, s2>>>();
    k_scanB<<<1, 128, 0, s2>>>();
    k_scanC<<<NSCB, SCB, 0, s2>>>();
    k_scatter<<<(NT + 255) / 256, 256, 0, s2>>>(trip);
    cudaEventRecord(evJoin, s2);

    // --- GEMM chain (default stream) ---
    k_prepB<<<(3 * 16384 + 255) / 256, 256>>>(Wa, Wg);
    k_relgemm<<<NR, 256>>>(emb_rel, Wa, Wg);
    k_mmagemm<<<(NE + 127) / 128, 256, SM_TOTAL>>>(emb_ent, ba, bg);

    cudaStreamWaitEvent(0, evJoin, 0);
    k_main<<<1184, 256>>>(av, out);
}

// round 11
// speedup vs baseline: 1.6207x; 1.1219x over previous
#include <cuda_runtime.h>
#include <cuda_bf16.h>
#include <math.h>
#include <cstdint>

#define NE 50000
#define NR 64
#define NT 400000

typedef unsigned long long u64;

// Scratch (static __device__ — no runtime allocation)
__device__ float    g_T[NE * 256];    // [ent][0:128]=emb@Wa2 (head/att), [128:256]=emb@Wg1+bg (head/msg)
__device__ float    g_P1[NE * 128];   // emb@Wa1 + ba (tail/att)
__device__ float    g_RG[NR * 256];   // [rel][0:128]=emb_rel@Wa3, [128:256]=emb_rel@Wg2
__device__ int      g_rowptr[NE + 1];
__device__ int      g_cursor[NE];
__device__ unsigned g_elist[NT];      // head | (rel<<16)
__device__ int      g_bsum[128];
__device__ int      g_boff[128];
// Pre-transposed bf16 weight images: [group][n][k], group 0=Wa1, 1=Wa2, 2=Wg1
__device__ __align__(16) unsigned short g_Bhi[3 * 16384];
__device__ __align__(16) unsigned short g_Blo[3 * 16384];

// ==================== warp-MMA helpers (sm_80+ PTX, works on sm_103) ====================
__device__ __forceinline__ uint32_t smem_u32(const void* p) {
    uint32_t a;
    asm("{ .reg .u64 t; cvta.to.shared.u64 t, %1; cvt.u32.u64 %0, t; }" : "=r"(a) : "l"(p));
    return a;
}
__device__ __forceinline__ void ldx4(uint32_t r[4], uint32_t addr) {
    asm volatile("ldmatrix.sync.aligned.m8n8.x4.shared.b16 {%0,%1,%2,%3}, [%4];"
                 : "=r"(r[0]), "=r"(r[1]), "=r"(r[2]), "=r"(r[3]) : "r"(addr));
}
__device__ __forceinline__ void ldx2(uint32_t r[2], uint32_t addr) {
    asm volatile("ldmatrix.sync.aligned.m8n8.x2.shared.b16 {%0,%1}, [%2];"
                 : "=r"(r[0]), "=r"(r[1]) : "r"(addr));
}
__device__ __forceinline__ void mma_bf16(float d[4], const uint32_t a[4], const uint32_t b[2]) {
    asm volatile("mma.sync.aligned.m16n8k16.row.col.f32.bf16.bf16.f32 "
                 "{%0,%1,%2,%3}, {%4,%5,%6,%7}, {%8,%9}, {%0,%1,%2,%3};"
                 : "+f"(d[0]), "+f"(d[1]), "+f"(d[2]), "+f"(d[3])
                 : "r"(a[0]), "r"(a[1]), "r"(a[2]), "r"(a[3]), "r"(b[0]), "r"(b[1]));
}
__device__ __forceinline__ float tanh_fast(float x) {
    float y; asm("tanh.approx.f32 %0, %1;" : "=f"(y) : "f"(x)); return y;
}

// ---------------- CSR build ----------------
__global__ void k_zero() {
    int i = blockIdx.x * blockDim.x + threadIdx.x;
    if (i <= NE) g_rowptr[i] = 0;
}

__global__ void k_count(const int* __restrict__ trip) {
    int e = blockIdx.x * blockDim.x + threadIdx.x;
    if (e < NT) atomicAdd(&g_rowptr[trip[3 * e + 2]], 1);
}

// 3-stage parallel scan: per-block sums -> scan of 98 sums -> per-block prefix
#define SCB 512
#define NSCB ((NE + SCB - 1) / SCB)   // 98

__global__ void k_scanA() {
    __shared__ int wsum[16];
    int b = blockIdx.x, t = threadIdx.x, lane = t & 31, w = t >> 5;
    int idx = b * SCB + t;
    int v = (idx < NE) ? g_rowptr[idx] : 0;
    #pragma unroll
    for (int o = 16; o > 0; o >>= 1) v += __shfl_down_sync(0xffffffffu, v, o);
    if (lane == 0) wsum[w] = v;
    __syncthreads();
    if (t == 0) {
        int s = 0;
        #pragma unroll
        for (int i = 0; i < 16; i++) s += wsum[i];
        g_bsum[b] = s;
    }
}

__global__ void k_scanB() {  // 1 block, 128 threads: exclusive scan of NSCB block sums
    __shared__ int woff[4];
    int t = threadIdx.x, lane = t & 31, w = t >> 5;
    int v = (t < NSCB) ? g_bsum[t] : 0;
    int incl = v;
    #pragma unroll
    for (int o = 1; o < 32; o <<= 1) {
        int u = __shfl_up_sync(0xffffffffu, incl, o);
        if (lane >= o) incl += u;
    }
    if (lane == 31) woff[w] = incl;
    __syncthreads();
    int base = 0;
    for (int i = 0; i < w; i++) base += woff[i];
    if (t < NSCB) g_boff[t] = base + incl - v;
    if (t == 0) g_rowptr[NE] = NT;
}

__global__ void k_scanC() {
    __shared__ int wsum[16];
    int b = blockIdx.x, t = threadIdx.x, lane = t & 31, w = t >> 5;
    int idx = b * SCB + t;
    int v = (idx < NE) ? g_rowptr[idx] : 0;
    int incl = v;
    #pragma unroll
    for (int o = 1; o < 32; o <<= 1) {
        int u = __shfl_up_sync(0xffffffffu, incl, o);
        if (lane >= o) incl += u;
    }
    if (lane == 31) wsum[w] = incl;
    __syncthreads();
    if (w == 0 && lane < 16) {
        int x = wsum[lane];
        #pragma unroll
        for (int o = 1; o < 16; o <<= 1) {
            int u = __shfl_up_sync(0xffffu, x, o);
            if (lane >= o) x += u;
        }
        wsum[lane] = x;  // inclusive
    }
    __syncthreads();
    int excl = g_boff[b] + (w > 0 ? wsum[w - 1] : 0) + (incl - v);
    if (idx < NE) { g_rowptr[idx] = excl; g_cursor[idx] = excl; }
}

__global__ void k_scatter(const int* __restrict__ trip) {
    int e = blockIdx.x * blockDim.x + threadIdx.x;
    if (e < NT) {
        int h = trip[3 * e], r = trip[3 * e + 1], t = trip[3 * e + 2];
        int pos = atomicAdd(&g_cursor[t], 1);
        g_elist[pos] = (unsigned)h | ((unsigned)r << 16);
    }
}

// ---------------- weight prep: fp32 -> hi/lo bf16, transposed to [n][k] ----------------
__global__ void k_prepB(const float* __restrict__ Wa, const float* __restrict__ Wg) {
    int idx = blockIdx.x * blockDim.x + threadIdx.x;
    if (idx >= 3 * 16384) return;
    int g = idx >> 14, rem = idx & 16383;
    int n = rem >> 7, k = rem & 127;
    float w = (g == 0) ? Wa[k * 128 + n] : (g == 1) ? Wa[(128 + k) * 128 + n] : Wg[k * 128 + n];
    __nv_bfloat16 hi = __float2bfloat16(w);
    __nv_bfloat16 lo = __float2bfloat16(w - __bfloat162float(hi));
    unsigned short hb, lb;
    memcpy(&hb, &hi, 2); memcpy(&lb, &lo, 2);
    g_Bhi[idx] = hb;
    g_Blo[idx] = lb;
}

// ---------------- tiny relation GEMM (fp32, exact) ----------------
__global__ void k_relgemm(const float* __restrict__ emb_rel,
                          const float* __restrict__ Wa,
                          const float* __restrict__ Wg) {
    __shared__ float er[128];
    int r = blockIdx.x;
    int tid = threadIdx.x;  // 256
    if (tid < 128) er[tid] = emb_rel[r * 128 + tid];
    __syncthreads();
    int j = tid & 127;
    const float* W = (tid < 128) ? (Wa + 256 * 128) : (Wg + 128 * 128);
    float acc = 0.f;
    #pragma unroll 8
    for (int k = 0; k < 128; k++) acc += er[k] * W[k * 128 + j];
    g_RG[r * 256 + tid] = acc;
}

// ---------------- HMMA entity GEMM: block M64 x (3 x N128) x K128, bf16 hi/lo 3-pass ----------------
// M64 tile: smem = 104448B -> 2 blocks/SM (16 warps) for latency hiding.
#define SROW 272
#define SM_A_HI 0
#define SM_A_LO 17408
#define SM_B_HI 34816
#define SM_B_LO 69632
#define SM_TOTAL 104448

__global__ __launch_bounds__(256, 2) void k_mmagemm(const float* __restrict__ A,
                                                    const float* __restrict__ ba,
                                                    const float* __restrict__ bg) {
    extern __shared__ char smem[];
    uint32_t sb = smem_u32(smem);
    int tid = threadIdx.x, wid = tid >> 5, lane = tid & 31;
    int rowBase = blockIdx.x * 64;
    int warpM = wid & 1, warpN = wid >> 1;  // 2x4 warp grid: 32 rows x 32 cols each

    // ---- fill A once (fp32 -> bf16 hi/lo): 64 rows x 128 k ----
    for (int i = tid; i < 2048; i += 256) {
        int m = i >> 5, k4 = (i & 31) * 4;
        int gr = rowBase + m;
        float4 v = make_float4(0.f, 0.f, 0.f, 0.f);
        if (gr < NE) v = *(const float4*)(A + (long)gr * 128 + k4);
        __nv_bfloat16 h0 = __float2bfloat16(v.x), h1 = __float2bfloat16(v.y);
        __nv_bfloat16 h2 = __float2bfloat16(v.z), h3 = __float2bfloat16(v.w);
        __nv_bfloat16 l0 = __float2bfloat16(v.x - __bfloat162float(h0));
        __nv_bfloat16 l1 = __float2bfloat16(v.y - __bfloat162float(h1));
        __nv_bfloat16 l2 = __float2bfloat16(v.z - __bfloat162float(h2));
        __nv_bfloat16 l3 = __float2bfloat16(v.w - __bfloat162float(h3));
        int off = m * SROW + k4 * 2;
        __nv_bfloat162 hv0; hv0.x = h0; hv0.y = h1;
        __nv_bfloat162 hv1; hv1.x = h2; hv1.y = h3;
        __nv_bfloat162 lv0; lv0.x = l0; lv0.y = l1;
        __nv_bfloat162 lv1; lv1.x = l2; lv1.y = l3;
        *(__nv_bfloat162*)(smem + SM_A_HI + off) = hv0;
        *(__nv_bfloat162*)(smem + SM_A_HI + off + 4) = hv1;
        *(__nv_bfloat162*)(smem + SM_A_LO + off) = lv0;
        *(__nv_bfloat162*)(smem + SM_A_LO + off + 4) = lv1;
    }

    uint32_t aAddr = sb + SM_A_HI + (uint32_t)((warpM * 32 + (lane & 15)) * SROW + ((lane >> 4) * 8) * 2);
    uint32_t bAddr = sb + SM_B_HI + (uint32_t)((warpN * 32 + (lane & 7)) * SROW + (((lane >> 3) & 1) * 8) * 2);

    int lrow = lane >> 2, lcol = (lane & 3) * 2;

    for (int g = 0; g < 3; g++) {
        // ---- fill B for this group: 128 rows x 128 k hi/lo ----
        {
            const uint4* sh = (const uint4*)(g_Bhi + g * 16384);
            const uint4* sl = (const uint4*)(g_Blo + g * 16384);
            for (int i = tid; i < 2048; i += 256) {
                int row = i >> 4, c = i & 15;
                int off = row * SROW + c * 16;
                *(uint4*)(smem + SM_B_HI + off) = sh[i];
                *(uint4*)(smem + SM_B_LO + off) = sl[i];
            }
        }
        __syncthreads();

        float acc[2][4][4];
        #pragma unroll
        for (int mt = 0; mt < 2; mt++)
            #pragma unroll
            for (int nt = 0; nt < 4; nt++)
                #pragma unroll
                for (int j = 0; j < 4; j++) acc[mt][nt][j] = 0.f;

        #pragma unroll
        for (int k = 0; k < 8; k++) {
            uint32_t ah[2][4], al[2][4];
            #pragma unroll
            for (int mt = 0; mt < 2; mt++) {
                ldx4(ah[mt], aAddr + mt * (16 * SROW) + k * 32);
                ldx4(al[mt], aAddr + mt * (16 * SROW) + k * 32 + (SM_A_LO - SM_A_HI));
            }
            #pragma unroll
            for (int nt = 0; nt < 4; nt++) {
                uint32_t bh[2], bl[2];
                uint32_t bo = bAddr + nt * (8 * SROW) + k * 32;
                ldx2(bh, bo);
                ldx2(bl, bo + (SM_B_LO - SM_B_HI));
                #pragma unroll
                for (int mt = 0; mt < 2; mt++) {
                    mma_bf16(acc[mt][nt], ah[mt], bh);
                    mma_bf16(acc[mt][nt], ah[mt], bl);
                    mma_bf16(acc[mt][nt], al[mt], bh);
                }
            }
        }
        __syncthreads();  // all warps done reading B before next-group overwrite

        // ---- epilogue for this group ----
        const float* bias = (g == 0) ? ba : (g == 2) ? bg : nullptr;
        float* base = (g == 0) ? g_P1 : g_T;
        int stride = (g == 0) ? 128 : 256;
        int coff = (g == 2) ? 128 : 0;

        #pragma unroll
        for (int mt = 0; mt < 2; mt++) {
            int r0 = rowBase + warpM * 32 + mt * 16 + lrow;
            int r1 = r0 + 8;
            #pragma unroll
            for (int nt = 0; nt < 4; nt++) {
                int n = warpN * 32 + nt * 8 + lcol;
                float b0 = 0.f, b1 = 0.f;
                if (bias) { b0 = __ldg(bias + n); b1 = __ldg(bias + n + 1); }
                if (r0 < NE) {
                    float2 v = make_float2(acc[mt][nt][0] + b0, acc[mt][nt][1] + b1);
                    *(float2*)(base + (long)r0 * stride + coff + n) = v;
                }
                if (r1 < NE) {
                    float2 v = make_float2(acc[mt][nt][2] + b0, acc[mt][nt][3] + b1);
                    *(float2*)(base + (long)r1 * stride + coff + n) = v;
                }
            }
        }
    }
}

// ---------------- fused edge kernel: pair-pipelined online softmax ----------------
struct Edge { float4 tlo, thi, ra, gr; };

__device__ __forceinline__ void fetch_edge(int idx, int lane, const float4* RG, Edge& E) {
    unsigned pk = __ldg(&g_elist[idx]);
    int h = pk & 0xFFFFu, r = pk >> 16;
    const float4* T4 = (const float4*)(g_T + (long)h * 256);
    E.tlo = __ldg(&T4[lane]);
    E.thi = __ldg(&T4[32 + lane]);
    E.ra  = __ldg(&RG[r * 64 + lane]);
    E.gr  = __ldg(&RG[r * 64 + 32 + lane]);
}

__device__ __forceinline__ void consume(const Edge& E, const float4& p1, const float4& av,
                                        float4& sA, float4& sG, float4& acc, float& m, float& s) {
    sA.x += E.ra.x; sA.y += E.ra.y; sA.z += E.ra.z; sA.w += E.ra.w;
    sG.x += E.gr.x; sG.y += E.gr.y; sG.z += E.gr.z; sG.w += E.gr.w;
    float hx = tanh_fast(p1.x + E.tlo.x + E.ra.x);
    float hy = tanh_fast(p1.y + E.tlo.y + E.ra.y);
    float hz = tanh_fast(p1.z + E.tlo.z + E.ra.z);
    float hw = tanh_fast(p1.w + E.tlo.w + E.ra.w);
    float part = hx * av.x + hy * av.y + hz * av.z + hw * av.w;
    part += __shfl_xor_sync(0xffffffffu, part, 1);
    part += __shfl_xor_sync(0xffffffffu, part, 2);
    float nm = fmaxf(m, part);
    float f = __expf(m - nm);
    float w = __expf(part - nm);
    s = s * f + w;
    acc.x = acc.x * f + w * (E.thi.x + E.gr.x);
    acc.y = acc.y * f + w * (E.thi.y + E.gr.y);
    acc.z = acc.z * f + w * (E.thi.z + E.gr.z);
    acc.w = acc.w * f + w * (E.thi.w + E.gr.w);
    m = nm;
}

__global__ __launch_bounds__(256) void k_main(const float* __restrict__ av_g,
                                              float* __restrict__ out) {
    int tid = threadIdx.x, lane = tid & 31, warp = tid >> 5;
    float4 av = ((const float4*)av_g)[lane];
    const float4* RG = (const float4*)g_RG;

    int gw = blockIdx.x * 8 + warp;
    int nw = gridDim.x * 8;
    for (int ent = gw; ent < NE; ent += nw) {
        int beg = g_rowptr[ent], end = g_rowptr[ent + 1];
        float4 p1 = *(const float4*)(g_P1 + (long)ent * 128 + lane * 4);
        float4 sA = make_float4(0.f, 0.f, 0.f, 0.f);
        float4 sG = sA, acc = sA;
        float m = -1e30f, s = 0.f;

        int deg = end - beg;
        int end2 = beg + (deg & ~1);  // paired portion

        Edge E0, E1;
        if (beg < end2) { fetch_edge(beg, lane, RG, E0); fetch_edge(beg + 1, lane, RG, E1); }
        for (int i = beg; i < end2; i += 2) {
            Edge C0 = E0, C1 = E1;
            if (i + 3 < end2 + 1) {
                fetch_edge(i + 2, lane, RG, E0);
                fetch_edge(i + 3, lane, RG, E1);
            }
            consume(C0, p1, av, sA, sG, acc, m, s);
            consume(C1, p1, av, sA, sG, acc, m, s);
        }
        if (end2 < end) {  // odd tail edge
            Edge Et;
            fetch_edge(end2, lane, RG, Et);
            consume(Et, p1, av, sA, sG, acc, m, s);
        }

        // self-loop edge: rel term = (sum Ra[rel]) / freq
        {
            float inv = (deg > 0) ? 1.f / (float)deg : 1.f;
            Edge Es;
            const float4* T4 = (const float4*)(g_T + (long)ent * 256);
            Es.tlo = __ldg(&T4[lane]);
            Es.thi = __ldg(&T4[32 + lane]);
            Es.ra = make_float4(sA.x * inv, sA.y * inv, sA.z * inv, sA.w * inv);
            Es.gr = make_float4(sG.x * inv, sG.y * inv, sG.z * inv, sG.w * inv);
            float4 dummyA = make_float4(0, 0, 0, 0), dummyG = dummyA;
            consume(Es, p1, av, dummyA, dummyG, acc, m, s);
        }
        float invs = 1.f / (s + 1e-16f);
        float4 o = make_float4(acc.x * invs, acc.y * invs, acc.z * invs, acc.w * invs);
        *(float4*)(out + (long)ent * 128 + lane * 4) = o;
    }
}

extern "C" void kernel_launch(void* const* d_in, const int* in_sizes, int n_in,
                              void* d_out, int out_size) {
    const float* emb_ent = (const float*)d_in[0];
    const float* emb_rel = (const float*)d_in[1];
    const int*   trip    = (const int*)d_in[2];
    const float* Wa      = (const float*)d_in[3];
    const float* ba      = (const float*)d_in[4];
    const float* av      = (const float*)d_in[5];
    const float* Wg      = (const float*)d_in[6];
    const float* bg      = (const float*)d_in[7];
    float* out = (float*)d_out;

    static cudaStream_t s2 = nullptr;
    static cudaEvent_t evFork = nullptr, evJoin = nullptr;
    if (!s2) {
        cudaStreamCreateWithFlags(&s2, cudaStreamNonBlocking);
        cudaEventCreateWithFlags(&evFork, cudaEventDisableTiming);
        cudaEventCreateWithFlags(&evJoin, cudaEventDisableTiming);
        cudaFuncSetAttribute(k_mmagemm, cudaFuncAttributeMaxDynamicSharedMemorySize, SM_TOTAL);
    }

    // fork: CSR chain + relgemm on s2, GEMM chain on default stream, join before k_main.
    // Submission order puts k_mmagemm at launch #6 so the fixed ncu window (-s 5 -c 1)
    // finally profiles it.
    cudaEventRecord(evFork, 0);
    cudaStreamWaitEvent(s2, evFork, 0);

    k_zero<<<(NE + 1 + 255) / 256, 256, 0, s2>>>();                 // 1
    k_count<<<(NT + 255) / 256, 256, 0, s2>>>(trip);                // 2
    k_prepB<<<(3 * 16384 + 255) / 256, 256>>>(Wa, Wg);              // 3 (s0)
    k_relgemm<<<NR, 256, 0, s2>>>(emb_rel, Wa, Wg);                 // 4
    k_scanA<<<NSCB, SCB, 0, s2>>>();                                // 5
    k_mmagemm<<<(NE + 63) / 64, 256, SM_TOTAL>>>(emb_ent, ba, bg);  // 6 (s0) <- profiled
    k_scanB<<<1, 128, 0, s2>>>();                                   // 7
    k_scanC<<<NSCB, SCB, 0, s2>>>();                                // 8
    k_scatter<<<(NT + 255) / 256, 256, 0, s2>>>(trip);              // 9
    cudaEventRecord(evJoin, s2);

    cudaStreamWaitEvent(0, evJoin, 0);
    k_main<<<1184, 256>>>(av, out);                                 // 10
}